// round 13
// baseline (speedup 1.0000x reference)
#include <cuda_runtime.h>
#include <cuda_bf16.h>
#include <cstdint>
#include <math.h>

#define B_  4
#define T_  2048
#define D_  1024
#define NH_ 16
#define HD_ 64
#define BT_ (B_*T_)
#define KD  2048     // dedup GEMM contraction: [h(1024)|l(1024)]
#define KPH 128      // flash packed head dim: [h(64)|l(64)]

__device__ __align__(128) __nv_bfloat16 g_xp[(size_t)BT_*KD];
__device__ __align__(128) __nv_bfloat16 g_wp[4][(size_t)D_*KD];
__device__ __align__(128) __nv_bfloat16 g_ap[(size_t)BT_*KD];
__device__ __align__(128) __nv_bfloat16 g_qp[(size_t)B_*NH_*T_*KPH];
__device__ __align__(128) __nv_bfloat16 g_kp[(size_t)B_*NH_*T_*KPH];
__device__ __align__(128) __nv_bfloat16 g_vp[(size_t)B_*NH_*HD_*2*T_];

__device__ __forceinline__ uint32_t smem_u32(const void* p) {
    uint32_t a;
    asm("{ .reg .u64 t; cvta.to.shared.u64 t, %1; cvt.u32.u64 %0, t; }" : "=r"(a) : "l"(p));
    return a;
}
__device__ __forceinline__ void cp_async16(uint32_t s, const void* g) {
    asm volatile("cp.async.cg.shared.global [%0], [%1], 16;" :: "r"(s), "l"(g));
}
#define CP_COMMIT() asm volatile("cp.async.commit_group;" ::: "memory")
#define CP_WAIT1()  asm volatile("cp.async.wait_group 1;" ::: "memory")
#define CP_WAIT0()  asm volatile("cp.async.wait_group 0;" ::: "memory")
__device__ __forceinline__ void ldsm4(uint32_t addr, uint32_t r[4]) {
    asm volatile("ldmatrix.sync.aligned.m8n8.x4.shared.b16 {%0,%1,%2,%3}, [%4];"
                 : "=r"(r[0]), "=r"(r[1]), "=r"(r[2]), "=r"(r[3]) : "r"(addr));
}
__device__ __forceinline__ void mma16816(float d[4], const uint32_t a[4], const uint32_t b[2]) {
    asm volatile("mma.sync.aligned.m16n8k16.row.col.f32.bf16.bf16.f32 "
                 "{%0,%1,%2,%3}, {%4,%5,%6,%7}, {%8,%9}, {%0,%1,%2,%3};"
                 : "+f"(d[0]), "+f"(d[1]), "+f"(d[2]), "+f"(d[3])
                 : "r"(a[0]), "r"(a[1]), "r"(a[2]), "r"(a[3]), "r"(b[0]), "r"(b[1]));
}
__device__ __forceinline__ uint32_t bfpair(float x, float y) {
    __nv_bfloat162 t = __floats2bfloat162_rn(x, y);
    return *reinterpret_cast<uint32_t*>(&t);
}
__device__ __forceinline__ float bflo(float x) {
    return x - __bfloat162float(__float2bfloat16(x));
}

// ---------------- pack kernels (dedup [h|l]) ----------------
__global__ __launch_bounds__(256) void pack_a_kernel(const float* __restrict__ X)
{
    int idx = blockIdx.x * 256 + threadIdx.x;
    size_t e = (size_t)idx * 4;
    float4 v = reinterpret_cast<const float4*>(X)[idx];
    int m = (int)(e >> 10), k = (int)(e & 1023);
    uint32_t* dst = reinterpret_cast<uint32_t*>(g_xp + (size_t)m * KD);
    dst[(k >> 1) + 0] = bfpair(v.x, v.y);
    dst[(k >> 1) + 1] = bfpair(v.z, v.w);
    dst[((1024 + k) >> 1) + 0] = bfpair(bflo(v.x), bflo(v.y));
    dst[((1024 + k) >> 1) + 1] = bfpair(bflo(v.z), bflo(v.w));
}

__global__ __launch_bounds__(256) void pack_w_kernel(
    const float* __restrict__ Wq, const float* __restrict__ Wk,
    const float* __restrict__ Wv, const float* __restrict__ Wp)
{
    const float* W = (blockIdx.z == 0) ? Wq : (blockIdx.z == 1) ? Wk :
                     (blockIdx.z == 2) ? Wv : Wp;
    __nv_bfloat16* out = g_wp[blockIdx.z];
    __shared__ float tile[32][33];
    const int tid = threadIdx.x;
    const int n0 = blockIdx.x * 32, k0 = blockIdx.y * 32;
#pragma unroll
    for (int i = 0; i < 4; i++) {
        int kk = (tid >> 5) + i * 8;
        tile[kk][tid & 31] = W[(size_t)(k0 + kk) * D_ + n0 + (tid & 31)];
    }
    __syncthreads();
#pragma unroll
    for (int i = 0; i < 4; i++) {
        int nn = (tid >> 5) + i * 8, kl = tid & 31;
        float v = tile[kl][nn];
        __nv_bfloat16 hi = __float2bfloat16(v);
        size_t base = (size_t)(n0 + nn) * KD + (k0 + kl);
        out[base] = hi;
        out[base + 1024] = __float2bfloat16(v - __bfloat162float(hi));
    }
}

// ---------------- dedup HMMA GEMM (128x128, 32 real k per iter, 3 stages) ----------------
#define DSTAGE 32768
#define DSMEM (3 * DSTAGE)
#define DNIT (D_ / 32)     // 32

__device__ __forceinline__ uint32_t sw_off(int r, int g) {
    return (uint32_t)(r * 64 + ((g ^ ((r >> 1) & 3)) << 4));
}
__device__ __forceinline__ void load_stage2(uint32_t sbuf,
                                            const __nv_bfloat16* __restrict__ A,
                                            const __nv_bfloat16* __restrict__ B, int k)
{
    const int tid = threadIdx.x;
#pragma unroll
    for (int i = 0; i < 8; i++) {
        int ch = tid + i * 256;
        int reg = ch >> 9;
        int r = (ch & 511) >> 2, gc = ch & 3;
        const __nv_bfloat16* base = (reg & 2) ? B : A;
        int off = (reg & 1) ? 1024 : 0;
        cp_async16(sbuf + reg * 8192 + sw_off(r, gc),
                   base + (size_t)r * KD + off + k + gc * 8);
    }
}
__device__ __forceinline__ void mma_blk(float acc[2][8][4], const uint32_t a[2][4],
                                        const uint32_t bp[2][4], int off) {
#pragma unroll
    for (int mt = 0; mt < 2; mt++)
#pragma unroll
        for (int kk = 0; kk < 2; kk++) {
            uint32_t q0[2] = {bp[kk][0], bp[kk][2]};
            uint32_t q1[2] = {bp[kk][1], bp[kk][3]};
            mma16816(acc[mt][off + kk*2 + 0], a[mt], q0);
            mma16816(acc[mt][off + kk*2 + 1], a[mt], q1);
        }
}
__device__ __forceinline__ void gemm_main2(uint32_t smem,
                                           const __nv_bfloat16* __restrict__ A,
                                           const __nv_bfloat16* __restrict__ B,
                                           float acc[2][8][4])
{
    const int tid = threadIdx.x, lane = tid & 31, wid = tid >> 5;
    const int wm = (wid & 3) * 32, wn = (wid >> 2) * 64;
    for (int s = 0; s < 2; s++) { load_stage2(smem + s * DSTAGE, A, B, s * 32); CP_COMMIT(); }
    const int rA = wm + (lane & 15), rB = wn + (lane & 15), kgl = (lane >> 4) & 1;
    int st3 = 0, ld3 = 2;
    for (int ks = 0; ks < DNIT; ks++) {
        CP_WAIT1();
        __syncthreads();
        if (ks + 2 < DNIT) load_stage2(smem + ld3 * DSTAGE, A, B, (ks + 2) * 32);
        CP_COMMIT();
        uint32_t stb = smem + st3 * DSTAGE;
#pragma unroll
        for (int kh = 0; kh < 2; kh++) {
            const int kg = kh * 2 + kgl;
            uint32_t aH[2][4], aL[2][4], bx[2][4], by[2][4];
            ldsm4(stb + sw_off(rA, kg), aH[0]);
            ldsm4(stb + sw_off(rA + 16, kg), aH[1]);
            ldsm4(stb + 16384 + sw_off(rB, kg), bx[0]);
            ldsm4(stb + 16384 + sw_off(rB + 16, kg), bx[1]);
            mma_blk(acc, aH, bx, 0);
            ldsm4(stb + 16384 + sw_off(rB + 32, kg), by[0]);
            ldsm4(stb + 16384 + sw_off(rB + 48, kg), by[1]);
            mma_blk(acc, aH, by, 4);
            ldsm4(stb + 8192 + sw_off(rA, kg), aL[0]);
            ldsm4(stb + 8192 + sw_off(rA + 16, kg), aL[1]);
            mma_blk(acc, aL, bx, 0);
            mma_blk(acc, aL, by, 4);
            ldsm4(stb + 24576 + sw_off(rB, kg), bx[0]);
            ldsm4(stb + 24576 + sw_off(rB + 16, kg), bx[1]);
            mma_blk(acc, aH, bx, 0);
            ldsm4(stb + 24576 + sw_off(rB + 32, kg), by[0]);
            ldsm4(stb + 24576 + sw_off(rB + 48, kg), by[1]);
            mma_blk(acc, aH, by, 4);
        }
        st3 = (st3 == 2) ? 0 : st3 + 1;
        ld3 = (ld3 == 2) ? 0 : ld3 + 1;
    }
}

__global__ __launch_bounds__(256, 2) void qkv_gemm(
    const float* __restrict__ bq, const float* __restrict__ bk, const float* __restrict__ bv)
{
    extern __shared__ __align__(128) char smem[];
    uint32_t sb = smem_u32(smem);
    const int z = blockIdx.z;
    const int m0 = blockIdx.y * 128, n0 = blockIdx.x * 128;
    float acc[2][8][4] = {};
    gemm_main2(sb, g_xp + (size_t)m0 * KD, g_wp[z] + (size_t)n0 * KD, acc);

    const float* bias = (z == 0) ? bq : (z == 1) ? bk : bv;
    const int lane = threadIdx.x & 31, wid = threadIdx.x >> 5;
    const int wm = (wid & 3) * 32, wn = (wid >> 2) * 64;
    const int row_l = lane >> 2, col_l = (lane & 3) * 2;

    if (z <= 1) {
        const int h = (n0 + wn) >> 6;
        __nv_bfloat16* dstp = (z == 0) ? g_qp : g_kp;
#pragma unroll
        for (int mt = 0; mt < 2; mt++) {
            int mr = m0 + wm + mt * 16 + row_l;
            int bb = mr >> 11, t = mr & (T_ - 1);
            uint32_t* r0p = reinterpret_cast<uint32_t*>(dstp + ((size_t)(bb*NH_+h)*T_ + t) * KPH);
            uint32_t* r8p = r0p + 8 * (KPH / 2);
#pragma unroll
            for (int nt = 0; nt < 8; nt++) {
                int c = nt * 8 + col_l;
                float bxs = bias[n0+wn+c], bys = bias[n0+wn+c+1];
                float v0x = acc[mt][nt][0]+bxs, v0y = acc[mt][nt][1]+bys;
                float v1x = acc[mt][nt][2]+bxs, v1y = acc[mt][nt][3]+bys;
                int ci = nt * 4 + (lane & 3);
                r0p[ci] = bfpair(v0x, v0y); r0p[32+ci] = bfpair(bflo(v0x), bflo(v0y));
                r8p[ci] = bfpair(v1x, v1y); r8p[32+ci] = bfpair(bflo(v1x), bflo(v1y));
            }
        }
    } else {
        // fused V transpose-pack via (dead) stage smem
        float* vt = reinterpret_cast<float*>(smem);
        __syncthreads();
#pragma unroll
        for (int mt = 0; mt < 2; mt++) {
            int rl = wm + mt * 16 + row_l;
#pragma unroll
            for (int nt = 0; nt < 8; nt++) {
                int cl = wn + nt * 8 + col_l;
                float bxs = bias[n0+cl], bys = bias[n0+cl+1];
                vt[rl * 130 + cl]           = acc[mt][nt][0] + bxs;
                vt[rl * 130 + cl + 1]       = acc[mt][nt][1] + bys;
                vt[(rl + 8) * 130 + cl]     = acc[mt][nt][2] + bxs;
                vt[(rl + 8) * 130 + cl + 1] = acc[mt][nt][3] + bys;
            }
        }
        __syncthreads();
        const int tid = threadIdx.x;
        const int c_loc = tid >> 1, half = tid & 1;
        const int h = (n0 + c_loc) >> 6;
        const int c = c_loc & 63;
        const int bb = m0 >> 11, t0 = m0 & (T_ - 1);
        const int bh = bb * NH_ + h;
        const int tl = (t0 >> 6) + half;
        uint32_t outbuf[64];
#pragma unroll
        for (int grp = 0; grp < 2; grp++)
#pragma unroll
            for (int sl2 = 0; sl2 < 16; sl2++) {
                float v0 = vt[(half*64 + grp*32 + 2*sl2)     * 130 + c_loc];
                float v1 = vt[(half*64 + grp*32 + 2*sl2 + 1) * 130 + c_loc];
                outbuf[grp*32 + sl2]      = bfpair(v0, v1);
                outbuf[grp*32 + 16 + sl2] = bfpair(bflo(v0), bflo(v1));
            }
        uint4* dst = reinterpret_cast<uint4*>(
            g_vp + (size_t)bh * HD_ * 2 * T_ + (size_t)c * 2 * T_ + tl * 128);
#pragma unroll
        for (int q = 0; q < 16; q++) dst[q] = reinterpret_cast<uint4*>(outbuf)[q];
    }
}

__global__ __launch_bounds__(256, 2) void proj_gemm(const float* __restrict__ bp, float* __restrict__ outC)
{
    extern __shared__ __align__(128) char smem[];
    uint32_t sb = smem_u32(smem);
    const int m0 = blockIdx.y * 128, n0 = blockIdx.x * 128;
    float acc[2][8][4] = {};
    gemm_main2(sb, g_ap + (size_t)m0 * KD, g_wp[3] + (size_t)n0 * KD, acc);
    const int lane = threadIdx.x & 31, wid = threadIdx.x >> 5;
    const int wm = (wid & 3) * 32, wn = (wid >> 2) * 64;
    const int row_l = lane >> 2, col_l = (lane & 3) * 2;
#pragma unroll
    for (int mt = 0; mt < 2; mt++) {
        int m = m0 + wm + mt * 16 + row_l;
        float* r0p = outC + (size_t)m * D_;
        float* r8p = r0p + 8 * D_;
#pragma unroll
        for (int nt = 0; nt < 8; nt++) {
            int n = n0 + wn + nt * 8 + col_l;
            float2 bi = *reinterpret_cast<const float2*>(&bp[n]);
            float2 v0 = {acc[mt][nt][0]+bi.x, acc[mt][nt][1]+bi.y};
            float2 v1 = {acc[mt][nt][2]+bi.x, acc[mt][nt][3]+bi.y};
            *reinterpret_cast<float2*>(r0p + n) = v0;
            *reinterpret_cast<float2*>(r8p + n) = v1;
        }
    }
}

// ---------------- HMMA flash v3: 256 thr, 8 warps x (16 rows x 64 keys), Q in regs ----------------
// smem: Q 32KB @0 ; KV double buffer 32KB each (K 16KB + V 16KB). No merge area needed.
#define FQS 0
#define FKV 32768
#define FLASH_SMEM 98304
#define FTHREADS 256

__device__ __forceinline__ uint32_t off256(int r, int g) {
    return (uint32_t)(r * 256 + ((g ^ (r & 7)) << 4));
}
__device__ __forceinline__ void f_kv(uint32_t sb, const char* gk, const char* gv, int jt, int buf)
{
    const int tid = threadIdx.x;
    uint32_t ks = sb + FKV + buf * 32768;
    uint32_t vs = ks + 16384;
#pragma unroll
    for (int i = 0; i < 4; i++) {
        int ch = tid + i * FTHREADS;      // 0..1023
        int r = ch >> 4, gr = ch & 15;
        cp_async16(ks + off256(r, gr), gk + ((size_t)(jt*64 + r)*KPH + gr*8) * 2);
    }
#pragma unroll
    for (int i = 0; i < 4; i++) {
        int ch = tid + i * FTHREADS;
        int r = ch >> 4, gr = ch & 15;
        cp_async16(vs + off256(r, gr), gv + ((size_t)r*2*T_ + jt*128 + gr*8) * 2);
    }
}

__global__ void __launch_bounds__(FTHREADS, 2) flash_mma()
{
    extern __shared__ __align__(128) char sm[];
    uint32_t sb = smem_u32(sm);
    const int qt = (T_/128 - 1) - blockIdx.x;
    const int bh = blockIdx.y;
    const int tid = threadIdx.x, lane = tid & 31, w = tid >> 5;
    const int wm = w * 16;                 // 8 warps x 16 rows = 128 rows
    const int rowq = lane >> 2, colq = (lane & 3) * 2;
    const int rA = wm + (lane & 15), kgl = (lane >> 4) & 1;
    const int rB = lane & 15;

    const char* gq = (const char*)(g_qp + ((size_t)bh*T_ + (size_t)qt*128) * KPH);
    const char* gk = (const char*)(g_kp + (size_t)bh*T_*KPH);
    const char* gv = (const char*)(g_vp + (size_t)bh*HD_*2*T_);

#pragma unroll
    for (int i = 0; i < 8; i++) {
        int ch = tid + i * FTHREADS;       // 0..2047
        int r = ch >> 4, gr = ch & 15;
        cp_async16(sb + FQS + off256(r, gr), gq + ((size_t)r*KPH + gr*8) * 2);
    }
    f_kv(sb, gk, gv, 0, 0);
    CP_COMMIT();
    CP_WAIT0();
    __syncthreads();

    // Q hoisted to registers (invariant across the KV loop)
    uint32_t Qh[4][4], Ql[4][4];
#pragma unroll
    for (int j = 0; j < 4; j++) {
        ldsm4(sb + FQS + off256(rA, 2*j + kgl), Qh[j]);
        ldsm4(sb + FQS + off256(rA, 8 + 2*j + kgl), Ql[j]);
    }

    float O[8][4] = {};
    float mr[2] = {-1e30f, -1e30f};
    float lr[2] = {0.f, 0.f};              // per-thread partial row sums

    const int njt = 2 * qt + 2;
    for (int jt = 0; jt < njt; jt++) {
        const int buf = jt & 1;
        if (jt > 0) { CP_WAIT0(); __syncthreads(); }
        if (jt + 1 < njt) { f_kv(sb, gk, gv, jt + 1, buf ^ 1); CP_COMMIT(); }

        const int dk = (jt - 2 * qt) * 64;
        const bool in_diag = (jt >= 2 * qt);
        if (in_diag && dk > wm + 15) continue;   // warp tile fully masked

        // ---- S = QK^T (16 rows x 64 keys), 3-term, Q from regs ----
        float s[8][4] = {};
        {
            uint32_t kS = sb + FKV + buf * 32768;
#pragma unroll
            for (int j = 0; j < 4; j++) {
                const int grh = 2 * j + kgl, grl = grh + 8;
#pragma unroll
                for (int th = 0; th < 2; th++) {
                    uint32_t b0[4], b1[4];
                    ldsm4(kS + off256(rB + 32*th, grh), b0);
                    ldsm4(kS + off256(rB + 32*th + 16, grh), b1);
                    uint32_t p00[2] = {b0[0], b0[2]}, p01[2] = {b0[1], b0[3]};
                    uint32_t p10[2] = {b1[0], b1[2]}, p11[2] = {b1[1], b1[3]};
                    mma16816(s[4*th+0], Qh[j], p00);
                    mma16816(s[4*th+1], Qh[j], p01);
                    mma16816(s[4*th+2], Qh[j], p10);
                    mma16816(s[4*th+3], Qh[j], p11);
                    mma16816(s[4*th+0], Ql[j], p00);
                    mma16816(s[4*th+1], Ql[j], p01);
                    mma16816(s[4*th+2], Ql[j], p10);
                    mma16816(s[4*th+3], Ql[j], p11);
                }
#pragma unroll
                for (int th = 0; th < 2; th++) {
                    uint32_t b0[4], b1[4];
                    ldsm4(kS + off256(rB + 32*th, grl), b0);
                    ldsm4(kS + off256(rB + 32*th + 16, grl), b1);
                    uint32_t p00[2] = {b0[0], b0[2]}, p01[2] = {b0[1], b0[3]};
                    uint32_t p10[2] = {b1[0], b1[2]}, p11[2] = {b1[1], b1[3]};
                    mma16816(s[4*th+0], Qh[j], p00);
                    mma16816(s[4*th+1], Qh[j], p01);
                    mma16816(s[4*th+2], Qh[j], p10);
                    mma16816(s[4*th+3], Qh[j], p11);
                }
            }
        }
        // mask only where the diagonal crosses this 16x64 tile
        if (in_diag && dk + 63 > wm) {
            const int rg0 = wm + rowq;
            const int cg0 = dk + colq;
#pragma unroll
            for (int nt = 0; nt < 8; nt++)
#pragma unroll
                for (int e = 0; e < 4; e++)
                    if (cg0 + nt * 8 + (e & 1) > rg0 + (e >> 1) * 8)
                        s[nt][e] = -1e30f;
        }
        // ---- online softmax over 64 keys (per 8-row group), deferred l ----
        float psc[2];
#pragma unroll
        for (int rg = 0; rg < 2; rg++) {
            float tm = -1e30f;
#pragma unroll
            for (int nt = 0; nt < 8; nt++)
                tm = fmaxf(tm, fmaxf(s[nt][rg*2], s[nt][rg*2+1]));
            tm = fmaxf(tm, __shfl_xor_sync(0xffffffffu, tm, 1));
            tm = fmaxf(tm, __shfl_xor_sync(0xffffffffu, tm, 2));
            float mn = fmaxf(mr[rg], tm);
            float sc = __expf(mr[rg] - mn);
            float rs = 0.0f;
#pragma unroll
            for (int nt = 0; nt < 8; nt++) {
                float p0 = __expf(s[nt][rg*2] - mn);
                float p1 = __expf(s[nt][rg*2+1] - mn);
                s[nt][rg*2] = p0; s[nt][rg*2+1] = p1;
                rs += p0 + p1;
            }
            lr[rg] = lr[rg] * sc + rs;
            mr[rg] = mn;
            psc[rg] = sc;
        }
#pragma unroll
        for (int ot = 0; ot < 8; ot++) {
            O[ot][0] *= psc[0]; O[ot][1] *= psc[0];
            O[ot][2] *= psc[1]; O[ot][3] *= psc[1];
        }
        // ---- P fragments in registers (replace s storage) ----
        uint32_t hiA[4][4], loA[4][4];
#pragma unroll
        for (int f = 0; f < 4; f++) {
            const float* s0 = s[2*f];
            const float* s1 = s[2*f+1];
            hiA[f][0] = bfpair(s0[0], s0[1]);
            hiA[f][1] = bfpair(s0[2], s0[3]);
            hiA[f][2] = bfpair(s1[0], s1[1]);
            hiA[f][3] = bfpair(s1[2], s1[3]);
            loA[f][0] = bfpair(bflo(s0[0]), bflo(s0[1]));
            loA[f][1] = bfpair(bflo(s0[2]), bflo(s0[3]));
            loA[f][2] = bfpair(bflo(s1[0]), bflo(s1[1]));
            loA[f][3] = bfpair(bflo(s1[2]), bflo(s1[3]));
        }
        // ---- O += P·V (3-term), V 64x64 ----
        {
            uint32_t vS = sb + FKV + buf * 32768 + 16384;
            const int rV = lane & 15;
#pragma unroll
            for (int gg = 0; gg < 2; gg++)
#pragma unroll
            for (int jj = 0; jj < 2; jj++) {
                const int f = gg * 2 + jj;
                const int grh = 8*gg + 2*jj + kgl, grl = grh + 4;
#pragma unroll
                for (int th = 0; th < 2; th++) {
                    uint32_t b0[4], b1[4];
                    ldsm4(vS + off256(rV + 32*th, grh), b0);
                    ldsm4(vS + off256(rV + 32*th + 16, grh), b1);
                    uint32_t p00[2] = {b0[0], b0[2]}, p01[2] = {b0[1], b0[3]};
                    uint32_t p10[2] = {b1[0], b1[2]}, p11[2] = {b1[1], b1[3]};
                    mma16816(O[4*th+0], hiA[f], p00);
                    mma16816(O[4*th+1], hiA[f], p01);
                    mma16816(O[4*th+2], hiA[f], p10);
                    mma16816(O[4*th+3], hiA[f], p11);
                    mma16816(O[4*th+0], loA[f], p00);
                    mma16816(O[4*th+1], loA[f], p01);
                    mma16816(O[4*th+2], loA[f], p10);
                    mma16816(O[4*th+3], loA[f], p11);
                    ldsm4(vS + off256(rV + 32*th, grl), b0);
                    ldsm4(vS + off256(rV + 32*th + 16, grl), b1);
                    uint32_t q00[2] = {b0[0], b0[2]}, q01[2] = {b0[1], b0[3]};
                    uint32_t q10[2] = {b1[0], b1[2]}, q11[2] = {b1[1], b1[3]};
                    mma16816(O[4*th+0], hiA[f], q00);
                    mma16816(O[4*th+1], hiA[f], q01);
                    mma16816(O[4*th+2], hiA[f], q10);
                    mma16816(O[4*th+3], hiA[f], q11);
                }
            }
        }
    }
    // ---- finalize: quad-reduce l, normalize, write packed g_ap (no cross-warp merge) ----
#pragma unroll
    for (int rg = 0; rg < 2; rg++) {
        lr[rg] += __shfl_xor_sync(0xffffffffu, lr[rg], 1);
        lr[rg] += __shfl_xor_sync(0xffffffffu, lr[rg], 2);
    }
    const int h = bh & 15, bb = bh >> 4;
#pragma unroll
    for (int rg = 0; rg < 2; rg++) {
        float inv = 1.0f / lr[rg];
        int t = qt * 128 + wm + rowq + rg * 8;
        uint32_t* dst = reinterpret_cast<uint32_t*>(g_ap + ((size_t)bb * T_ + t) * KD);
#pragma unroll
        for (int nt = 0; nt < 8; nt++) {
            int c = nt * 8 + colq;
            float v0 = O[nt][rg*2] * inv;
            float v1 = O[nt][rg*2+1] * inv;
            dst[(h * 64 + c) >> 1] = bfpair(v0, v1);
            dst[(1024 + h * 64 + c) >> 1] = bfpair(bflo(v0), bflo(v1));
        }
    }
}

// ---------------- launch ----------------
extern "C" void kernel_launch(void* const* d_in, const int* in_sizes, int n_in,
                              void* d_out, int out_size)
{
    const float* x  = (const float*)d_in[0];
    const float* Wk = (const float*)d_in[1];
    const float* bk = (const float*)d_in[2];
    const float* Wq = (const float*)d_in[3];
    const float* bq = (const float*)d_in[4];
    const float* Wv = (const float*)d_in[5];
    const float* bv = (const float*)d_in[6];
    const float* Wp = (const float*)d_in[7];
    const float* bp = (const float*)d_in[8];
    float* out = (float*)d_out;

    pack_a_kernel<<<(BT_ * D_) / (4 * 256), 256>>>(x);
    pack_w_kernel<<<dim3(32, 32, 4), 256>>>(Wq, Wk, Wv, Wp);

    cudaFuncSetAttribute(qkv_gemm, cudaFuncAttributeMaxDynamicSharedMemorySize, DSMEM);
    cudaFuncSetAttribute(proj_gemm, cudaFuncAttributeMaxDynamicSharedMemorySize, DSMEM);
    cudaFuncSetAttribute(flash_mma, cudaFuncAttributeMaxDynamicSharedMemorySize, FLASH_SMEM);

    qkv_gemm<<<dim3(8, 64, 3), 256, DSMEM>>>(bq, bk, bv);
    flash_mma<<<dim3(T_ / 128, B_ * NH_), FTHREADS, FLASH_SMEM>>>();
    proj_gemm<<<dim3(8, 64), 256, DSMEM>>>(bp, out);
}

// round 14
// speedup vs baseline: 1.0170x; 1.0170x over previous
#include <cuda_runtime.h>
#include <cuda_bf16.h>
#include <cstdint>
#include <math.h>

#define B_  4
#define T_  2048
#define D_  1024
#define NH_ 16
#define HD_ 64
#define BT_ (B_*T_)
#define KD  2048     // dedup GEMM contraction: [h(1024)|l(1024)]
#define KPH 128      // flash packed head dim: [h(64)|l(64)]

__device__ __align__(128) __nv_bfloat16 g_xp[(size_t)BT_*KD];
__device__ __align__(128) __nv_bfloat16 g_wp[4][(size_t)D_*KD];
__device__ __align__(128) __nv_bfloat16 g_ap[(size_t)BT_*KD];
__device__ __align__(128) __nv_bfloat16 g_qp[(size_t)B_*NH_*T_*KPH];
__device__ __align__(128) __nv_bfloat16 g_kp[(size_t)B_*NH_*T_*KPH];
__device__ __align__(128) __nv_bfloat16 g_vp[(size_t)B_*NH_*HD_*2*T_];

__device__ __forceinline__ uint32_t smem_u32(const void* p) {
    uint32_t a;
    asm("{ .reg .u64 t; cvta.to.shared.u64 t, %1; cvt.u32.u64 %0, t; }" : "=r"(a) : "l"(p));
    return a;
}
__device__ __forceinline__ void cp_async16(uint32_t s, const void* g) {
    asm volatile("cp.async.cg.shared.global [%0], [%1], 16;" :: "r"(s), "l"(g));
}
#define CP_COMMIT() asm volatile("cp.async.commit_group;" ::: "memory")
#define CP_WAIT1()  asm volatile("cp.async.wait_group 1;" ::: "memory")
#define CP_WAIT0()  asm volatile("cp.async.wait_group 0;" ::: "memory")
__device__ __forceinline__ void ldsm4(uint32_t addr, uint32_t r[4]) {
    asm volatile("ldmatrix.sync.aligned.m8n8.x4.shared.b16 {%0,%1,%2,%3}, [%4];"
                 : "=r"(r[0]), "=r"(r[1]), "=r"(r[2]), "=r"(r[3]) : "r"(addr));
}
__device__ __forceinline__ void mma16816(float d[4], const uint32_t a[4], const uint32_t b[2]) {
    asm volatile("mma.sync.aligned.m16n8k16.row.col.f32.bf16.bf16.f32 "
                 "{%0,%1,%2,%3}, {%4,%5,%6,%7}, {%8,%9}, {%0,%1,%2,%3};"
                 : "+f"(d[0]), "+f"(d[1]), "+f"(d[2]), "+f"(d[3])
                 : "r"(a[0]), "r"(a[1]), "r"(a[2]), "r"(a[3]), "r"(b[0]), "r"(b[1]));
}
__device__ __forceinline__ uint32_t bfpair(float x, float y) {
    __nv_bfloat162 t = __floats2bfloat162_rn(x, y);
    return *reinterpret_cast<uint32_t*>(&t);
}
__device__ __forceinline__ float bflo(float x) {
    return x - __bfloat162float(__float2bfloat16(x));
}

// ---------------- pack kernels (dedup [h|l]) ----------------
__global__ __launch_bounds__(256) void pack_a_kernel(const float* __restrict__ X)
{
    int idx = blockIdx.x * 256 + threadIdx.x;
    size_t e = (size_t)idx * 4;
    float4 v = reinterpret_cast<const float4*>(X)[idx];
    int m = (int)(e >> 10), k = (int)(e & 1023);
    uint32_t* dst = reinterpret_cast<uint32_t*>(g_xp + (size_t)m * KD);
    dst[(k >> 1) + 0] = bfpair(v.x, v.y);
    dst[(k >> 1) + 1] = bfpair(v.z, v.w);
    dst[((1024 + k) >> 1) + 0] = bfpair(bflo(v.x), bflo(v.y));
    dst[((1024 + k) >> 1) + 1] = bfpair(bflo(v.z), bflo(v.w));
}

__global__ __launch_bounds__(256) void pack_w_kernel(
    const float* __restrict__ Wq, const float* __restrict__ Wk,
    const float* __restrict__ Wv, const float* __restrict__ Wp)
{
    const float* W = (blockIdx.z == 0) ? Wq : (blockIdx.z == 1) ? Wk :
                     (blockIdx.z == 2) ? Wv : Wp;
    __nv_bfloat16* out = g_wp[blockIdx.z];
    __shared__ float tile[32][33];
    const int tid = threadIdx.x;
    const int n0 = blockIdx.x * 32, k0 = blockIdx.y * 32;
#pragma unroll
    for (int i = 0; i < 4; i++) {
        int kk = (tid >> 5) + i * 8;
        tile[kk][tid & 31] = W[(size_t)(k0 + kk) * D_ + n0 + (tid & 31)];
    }
    __syncthreads();
#pragma unroll
    for (int i = 0; i < 4; i++) {
        int nn = (tid >> 5) + i * 8, kl = tid & 31;
        float v = tile[kl][nn];
        __nv_bfloat16 hi = __float2bfloat16(v);
        size_t base = (size_t)(n0 + nn) * KD + (k0 + kl);
        out[base] = hi;
        out[base + 1024] = __float2bfloat16(v - __bfloat162float(hi));
    }
}

// ---------------- dedup HMMA GEMM (128x128, 32 real k per iter, 3 stages) ----------------
#define DSTAGE 32768
#define DSMEM (3 * DSTAGE)
#define DNIT (D_ / 32)     // 32

__device__ __forceinline__ uint32_t sw_off(int r, int g) {
    return (uint32_t)(r * 64 + ((g ^ ((r >> 1) & 3)) << 4));
}
__device__ __forceinline__ void load_stage2(uint32_t sbuf,
                                            const __nv_bfloat16* __restrict__ A,
                                            const __nv_bfloat16* __restrict__ B, int k)
{
    const int tid = threadIdx.x;
#pragma unroll
    for (int i = 0; i < 8; i++) {
        int ch = tid + i * 256;
        int reg = ch >> 9;
        int r = (ch & 511) >> 2, gc = ch & 3;
        const __nv_bfloat16* base = (reg & 2) ? B : A;
        int off = (reg & 1) ? 1024 : 0;
        cp_async16(sbuf + reg * 8192 + sw_off(r, gc),
                   base + (size_t)r * KD + off + k + gc * 8);
    }
}
__device__ __forceinline__ void mma_blk(float acc[2][8][4], const uint32_t a[2][4],
                                        const uint32_t bp[2][4], int off) {
#pragma unroll
    for (int mt = 0; mt < 2; mt++)
#pragma unroll
        for (int kk = 0; kk < 2; kk++) {
            uint32_t q0[2] = {bp[kk][0], bp[kk][2]};
            uint32_t q1[2] = {bp[kk][1], bp[kk][3]};
            mma16816(acc[mt][off + kk*2 + 0], a[mt], q0);
            mma16816(acc[mt][off + kk*2 + 1], a[mt], q1);
        }
}
__device__ __forceinline__ void gemm_main2(uint32_t smem,
                                           const __nv_bfloat16* __restrict__ A,
                                           const __nv_bfloat16* __restrict__ B,
                                           float acc[2][8][4])
{
    const int tid = threadIdx.x, lane = tid & 31, wid = tid >> 5;
    const int wm = (wid & 3) * 32, wn = (wid >> 2) * 64;
    for (int s = 0; s < 2; s++) { load_stage2(smem + s * DSTAGE, A, B, s * 32); CP_COMMIT(); }
    const int rA = wm + (lane & 15), rB = wn + (lane & 15), kgl = (lane >> 4) & 1;
    int st3 = 0, ld3 = 2;
    for (int ks = 0; ks < DNIT; ks++) {
        CP_WAIT1();
        __syncthreads();
        if (ks + 2 < DNIT) load_stage2(smem + ld3 * DSTAGE, A, B, (ks + 2) * 32);
        CP_COMMIT();
        uint32_t stb = smem + st3 * DSTAGE;
#pragma unroll
        for (int kh = 0; kh < 2; kh++) {
            const int kg = kh * 2 + kgl;
            uint32_t aH[2][4], aL[2][4], bx[2][4], by[2][4];
            ldsm4(stb + sw_off(rA, kg), aH[0]);
            ldsm4(stb + sw_off(rA + 16, kg), aH[1]);
            ldsm4(stb + 16384 + sw_off(rB, kg), bx[0]);
            ldsm4(stb + 16384 + sw_off(rB + 16, kg), bx[1]);
            mma_blk(acc, aH, bx, 0);
            ldsm4(stb + 16384 + sw_off(rB + 32, kg), by[0]);
            ldsm4(stb + 16384 + sw_off(rB + 48, kg), by[1]);
            mma_blk(acc, aH, by, 4);
            ldsm4(stb + 8192 + sw_off(rA, kg), aL[0]);
            ldsm4(stb + 8192 + sw_off(rA + 16, kg), aL[1]);
            mma_blk(acc, aL, bx, 0);
            mma_blk(acc, aL, by, 4);
            ldsm4(stb + 24576 + sw_off(rB, kg), bx[0]);
            ldsm4(stb + 24576 + sw_off(rB + 16, kg), bx[1]);
            mma_blk(acc, aH, bx, 0);
            ldsm4(stb + 24576 + sw_off(rB + 32, kg), by[0]);
            ldsm4(stb + 24576 + sw_off(rB + 48, kg), by[1]);
            mma_blk(acc, aH, by, 4);
        }
        st3 = (st3 == 2) ? 0 : st3 + 1;
        ld3 = (ld3 == 2) ? 0 : ld3 + 1;
    }
}

__global__ __launch_bounds__(256, 2) void qkv_gemm(
    const float* __restrict__ bq, const float* __restrict__ bk, const float* __restrict__ bv)
{
    extern __shared__ __align__(128) char smem[];
    uint32_t sb = smem_u32(smem);
    const int z = blockIdx.z;
    const int m0 = blockIdx.y * 128, n0 = blockIdx.x * 128;
    float acc[2][8][4] = {};
    gemm_main2(sb, g_xp + (size_t)m0 * KD, g_wp[z] + (size_t)n0 * KD, acc);

    const float* bias = (z == 0) ? bq : (z == 1) ? bk : bv;
    const int lane = threadIdx.x & 31, wid = threadIdx.x >> 5;
    const int wm = (wid & 3) * 32, wn = (wid >> 2) * 64;
    const int row_l = lane >> 2, col_l = (lane & 3) * 2;

    if (z <= 1) {
        const int h = (n0 + wn) >> 6;
        __nv_bfloat16* dstp = (z == 0) ? g_qp : g_kp;
#pragma unroll
        for (int mt = 0; mt < 2; mt++) {
            int mr = m0 + wm + mt * 16 + row_l;
            int bb = mr >> 11, t = mr & (T_ - 1);
            uint32_t* r0p = reinterpret_cast<uint32_t*>(dstp + ((size_t)(bb*NH_+h)*T_ + t) * KPH);
            uint32_t* r8p = r0p + 8 * (KPH / 2);
#pragma unroll
            for (int nt = 0; nt < 8; nt++) {
                int c = nt * 8 + col_l;
                float bxs = bias[n0+wn+c], bys = bias[n0+wn+c+1];
                float v0x = acc[mt][nt][0]+bxs, v0y = acc[mt][nt][1]+bys;
                float v1x = acc[mt][nt][2]+bxs, v1y = acc[mt][nt][3]+bys;
                int ci = nt * 4 + (lane & 3);
                r0p[ci] = bfpair(v0x, v0y); r0p[32+ci] = bfpair(bflo(v0x), bflo(v0y));
                r8p[ci] = bfpair(v1x, v1y); r8p[32+ci] = bfpair(bflo(v1x), bflo(v1y));
            }
        }
    } else {
        // fused V transpose-pack via (dead) stage smem
        float* vt = reinterpret_cast<float*>(smem);
        __syncthreads();
#pragma unroll
        for (int mt = 0; mt < 2; mt++) {
            int rl = wm + mt * 16 + row_l;
#pragma unroll
            for (int nt = 0; nt < 8; nt++) {
                int cl = wn + nt * 8 + col_l;
                float bxs = bias[n0+cl], bys = bias[n0+cl+1];
                vt[rl * 130 + cl]           = acc[mt][nt][0] + bxs;
                vt[rl * 130 + cl + 1]       = acc[mt][nt][1] + bys;
                vt[(rl + 8) * 130 + cl]     = acc[mt][nt][2] + bxs;
                vt[(rl + 8) * 130 + cl + 1] = acc[mt][nt][3] + bys;
            }
        }
        __syncthreads();
        const int tid = threadIdx.x;
        const int c_loc = tid >> 1, half = tid & 1;
        const int h = (n0 + c_loc) >> 6;
        const int c = c_loc & 63;
        const int bb = m0 >> 11, t0 = m0 & (T_ - 1);
        const int bh = bb * NH_ + h;
        const int tl = (t0 >> 6) + half;
        uint32_t outbuf[64];
#pragma unroll
        for (int grp = 0; grp < 2; grp++)
#pragma unroll
            for (int sl2 = 0; sl2 < 16; sl2++) {
                float v0 = vt[(half*64 + grp*32 + 2*sl2)     * 130 + c_loc];
                float v1 = vt[(half*64 + grp*32 + 2*sl2 + 1) * 130 + c_loc];
                outbuf[grp*32 + sl2]      = bfpair(v0, v1);
                outbuf[grp*32 + 16 + sl2] = bfpair(bflo(v0), bflo(v1));
            }
        uint4* dst = reinterpret_cast<uint4*>(
            g_vp + (size_t)bh * HD_ * 2 * T_ + (size_t)c * 2 * T_ + tl * 128);
#pragma unroll
        for (int q = 0; q < 16; q++) dst[q] = reinterpret_cast<uint4*>(outbuf)[q];
    }
}

__global__ __launch_bounds__(256, 2) void proj_gemm(const float* __restrict__ bp, float* __restrict__ outC)
{
    extern __shared__ __align__(128) char smem[];
    uint32_t sb = smem_u32(smem);
    const int m0 = blockIdx.y * 128, n0 = blockIdx.x * 128;
    float acc[2][8][4] = {};
    gemm_main2(sb, g_ap + (size_t)m0 * KD, g_wp[3] + (size_t)n0 * KD, acc);
    const int lane = threadIdx.x & 31, wid = threadIdx.x >> 5;
    const int wm = (wid & 3) * 32, wn = (wid >> 2) * 64;
    const int row_l = lane >> 2, col_l = (lane & 3) * 2;
#pragma unroll
    for (int mt = 0; mt < 2; mt++) {
        int m = m0 + wm + mt * 16 + row_l;
        float* r0p = outC + (size_t)m * D_;
        float* r8p = r0p + 8 * D_;
#pragma unroll
        for (int nt = 0; nt < 8; nt++) {
            int n = n0 + wn + nt * 8 + col_l;
            float2 bi = *reinterpret_cast<const float2*>(&bp[n]);
            float2 v0 = {acc[mt][nt][0]+bi.x, acc[mt][nt][1]+bi.y};
            float2 v1 = {acc[mt][nt][2]+bi.x, acc[mt][nt][3]+bi.y};
            *reinterpret_cast<float2*>(r0p + n) = v0;
            *reinterpret_cast<float2*>(r8p + n) = v1;
        }
    }
}

// ---------------- HMMA flash v4: 256 thr, 8 warps x (16 rows x 32 keys), Q in regs,
// 32KB smem -> 2 independent CTAs/SM (desynchronized softmax phases) ----------------
#define FLASH_SMEM 32768
#define FTHREADS 256

__device__ __forceinline__ uint32_t off256(int r, int g) {
    return (uint32_t)(r * 256 + ((g ^ (r & 7)) << 4));
}
__device__ __forceinline__ uint32_t off128(int r, int g) {
    return (uint32_t)(r * 128 + ((g ^ (r & 7)) << 4));
}
// KV stage (16KB): K 32 rows x 256B @ +0 ; V 64 rows x 128B @ +8192
__device__ __forceinline__ void f_kv(uint32_t sb, const char* gk, const char* gv, int jt, int buf)
{
    const int tid = threadIdx.x;
    uint32_t ks = sb + buf * 16384;
    uint32_t vs = ks + 8192;
#pragma unroll
    for (int i = 0; i < 2; i++) {
        int ch = tid + i * FTHREADS;      // 0..511
        int r = ch >> 4, gr = ch & 15;    // r in [0,32)
        cp_async16(ks + off256(r, gr), gk + ((size_t)(jt*32 + r)*KPH + gr*8) * 2);
    }
#pragma unroll
    for (int i = 0; i < 2; i++) {
        int ch = tid + i * FTHREADS;
        int r = ch >> 3, gr = ch & 7;     // r in [0,64)
        cp_async16(vs + off128(r, gr),
                   gv + ((size_t)r*2*T_ + (jt >> 1)*128 + (jt & 1)*64 + gr*8) * 2);
    }
}

__global__ void __launch_bounds__(FTHREADS, 2) flash_mma()
{
    extern __shared__ __align__(128) char sm[];
    uint32_t sb = smem_u32(sm);
    const int qt = (T_/128 - 1) - blockIdx.x;
    const int bh = blockIdx.y;
    const int tid = threadIdx.x, lane = tid & 31, w = tid >> 5;
    const int wm = w * 16;                 // 8 warps x 16 rows = 128 rows
    const int rowq = lane >> 2, colq = (lane & 3) * 2;
    const int rA = wm + (lane & 15), kgl = (lane >> 4) & 1;
    const int rB = lane & 15;

    const char* gq = (const char*)(g_qp + ((size_t)bh*T_ + (size_t)qt*128) * KPH);
    const char* gk = (const char*)(g_kp + (size_t)bh*T_*KPH);
    const char* gv = (const char*)(g_vp + (size_t)bh*HD_*2*T_);

    // ---- stage Q (32KB, overlapping both KV buffers), read to regs ----
#pragma unroll
    for (int i = 0; i < 8; i++) {
        int ch = tid + i * FTHREADS;       // 0..2047
        int r = ch >> 4, gr = ch & 15;
        cp_async16(sb + off256(r, gr), gq + ((size_t)r*KPH + gr*8) * 2);
    }
    CP_COMMIT();
    CP_WAIT0();
    __syncthreads();
    uint32_t Qh[4][4], Ql[4][4];
#pragma unroll
    for (int j = 0; j < 4; j++) {
        ldsm4(sb + off256(rA, 2*j + kgl), Qh[j]);
        ldsm4(sb + off256(rA, 8 + 2*j + kgl), Ql[j]);
    }
    __syncthreads();                       // all warps done reading Q smem
    f_kv(sb, gk, gv, 0, 0);
    CP_COMMIT();

    float O[8][4] = {};
    float mr[2] = {-1e30f, -1e30f};
    float lr[2] = {0.f, 0.f};              // per-thread partial row sums

    const int njt = 4 * qt + 4;            // 32-key tiles
    for (int jt = 0; jt < njt; jt++) {
        const int buf = jt & 1;
        CP_WAIT0();
        __syncthreads();
        if (jt + 1 < njt) { f_kv(sb, gk, gv, jt + 1, buf ^ 1); CP_COMMIT(); }

        const int dk = jt * 32 - qt * 128;
        const bool in_diag = (jt >= 4 * qt);
        if (in_diag && dk > wm + 15) continue;   // warp tile fully masked

        // ---- S = QK^T (16 rows x 32 keys), 3-term, Q from regs ----
        float s[4][4] = {};
        {
            uint32_t kS = sb + buf * 16384;
#pragma unroll
            for (int j = 0; j < 4; j++) {
                const int grh = 2*j + kgl, grl = 8 + 2*j + kgl;
                uint32_t b0[4], b1[4];
                ldsm4(kS + off256(rB, grh), b0);
                ldsm4(kS + off256(rB + 16, grh), b1);
                uint32_t p0[2] = {b0[0], b0[2]}, p1[2] = {b0[1], b0[3]};
                uint32_t p2[2] = {b1[0], b1[2]}, p3[2] = {b1[1], b1[3]};
                mma16816(s[0], Qh[j], p0);
                mma16816(s[1], Qh[j], p1);
                mma16816(s[2], Qh[j], p2);
                mma16816(s[3], Qh[j], p3);
                mma16816(s[0], Ql[j], p0);
                mma16816(s[1], Ql[j], p1);
                mma16816(s[2], Ql[j], p2);
                mma16816(s[3], Ql[j], p3);
                ldsm4(kS + off256(rB, grl), b0);
                ldsm4(kS + off256(rB + 16, grl), b1);
                uint32_t q0[2] = {b0[0], b0[2]}, q1[2] = {b0[1], b0[3]};
                uint32_t q2[2] = {b1[0], b1[2]}, q3[2] = {b1[1], b1[3]};
                mma16816(s[0], Qh[j], q0);
                mma16816(s[1], Qh[j], q1);
                mma16816(s[2], Qh[j], q2);
                mma16816(s[3], Qh[j], q3);
            }
        }
        // mask only where the diagonal crosses this 16x32 tile
        if (in_diag && dk + 31 > wm) {
            const int rg0 = wm + rowq;
            const int cg0 = dk + colq;
#pragma unroll
            for (int nt = 0; nt < 4; nt++)
#pragma unroll
                for (int e = 0; e < 4; e++)
                    if (cg0 + nt * 8 + (e & 1) > rg0 + (e >> 1) * 8)
                        s[nt][e] = -1e30f;
        }
        // ---- online softmax (per 8-row group), deferred l ----
        float psc[2];
#pragma unroll
        for (int rg = 0; rg < 2; rg++) {
            float tm = -1e30f;
#pragma unroll
            for (int nt = 0; nt < 4; nt++)
                tm = fmaxf(tm, fmaxf(s[nt][rg*2], s[nt][rg*2+1]));
            tm = fmaxf(tm, __shfl_xor_sync(0xffffffffu, tm, 1));
            tm = fmaxf(tm, __shfl_xor_sync(0xffffffffu, tm, 2));
            float mn = fmaxf(mr[rg], tm);
            float sc = __expf(mr[rg] - mn);
            float rs = 0.0f;
#pragma unroll
            for (int nt = 0; nt < 4; nt++) {
                float p0 = __expf(s[nt][rg*2] - mn);
                float p1 = __expf(s[nt][rg*2+1] - mn);
                s[nt][rg*2] = p0; s[nt][rg*2+1] = p1;
                rs += p0 + p1;
            }
            lr[rg] = lr[rg] * sc + rs;
            mr[rg] = mn;
            psc[rg] = sc;
        }
#pragma unroll
        for (int ot = 0; ot < 8; ot++) {
            O[ot][0] *= psc[0]; O[ot][1] *= psc[0];
            O[ot][2] *= psc[1]; O[ot][3] *= psc[1];
        }
        // ---- P fragments in registers ----
        uint32_t hiA[2][4], loA[2][4];
#pragma unroll
        for (int j2 = 0; j2 < 2; j2++) {
            const float* s0 = s[2*j2];
            const float* s1 = s[2*j2+1];
            hiA[j2][0] = bfpair(s0[0], s0[1]);
            hiA[j2][1] = bfpair(s0[2], s0[3]);
            hiA[j2][2] = bfpair(s1[0], s1[1]);
            hiA[j2][3] = bfpair(s1[2], s1[3]);
            loA[j2][0] = bfpair(bflo(s0[0]), bflo(s0[1]));
            loA[j2][1] = bfpair(bflo(s0[2]), bflo(s0[3]));
            loA[j2][2] = bfpair(bflo(s1[0]), bflo(s1[1]));
            loA[j2][3] = bfpair(bflo(s1[2]), bflo(s1[3]));
        }
        // ---- O += P·V (3-term): Ph·Vh + Ph·Vl + Pl·Vh ----
        {
            uint32_t vS = sb + buf * 16384 + 8192;
            const int rV = lane & 15;
#pragma unroll
            for (int jj = 0; jj < 2; jj++) {
                const int grh = 2*jj + kgl, grl = 4 + 2*jj + kgl;
                uint32_t c0[4], c1[4], c2[4], c3[4];
                ldsm4(vS + off128(rV, grh),      c0);
                ldsm4(vS + off128(rV + 16, grh), c1);
                ldsm4(vS + off128(rV + 32, grh), c2);
                ldsm4(vS + off128(rV + 48, grh), c3);
                {
                    uint32_t p0[2]={c0[0],c0[2]}, p1[2]={c0[1],c0[3]};
                    uint32_t p2[2]={c1[0],c1[2]}, p3[2]={c1[1],c1[3]};
                    uint32_t p4[2]={c2[0],c2[2]}, p5[2]={c2[1],c2[3]};
                    uint32_t p6[2]={c3[0],c3[2]}, p7[2]={c3[1],c3[3]};
                    mma16816(O[0], hiA[jj], p0); mma16816(O[1], hiA[jj], p1);
                    mma16816(O[2], hiA[jj], p2); mma16816(O[3], hiA[jj], p3);
                    mma16816(O[4], hiA[jj], p4); mma16816(O[5], hiA[jj], p5);
                    mma16816(O[6], hiA[jj], p6); mma16816(O[7], hiA[jj], p7);
                    mma16816(O[0], loA[jj], p0); mma16816(O[1], loA[jj], p1);
                    mma16816(O[2], loA[jj], p2); mma16816(O[3], loA[jj], p3);
                    mma16816(O[4], loA[jj], p4); mma16816(O[5], loA[jj], p5);
                    mma16816(O[6], loA[jj], p6); mma16816(O[7], loA[jj], p7);
                }
                ldsm4(vS + off128(rV, grl),      c0);
                ldsm4(vS + off128(rV + 16, grl), c1);
                ldsm4(vS + off128(rV + 32, grl), c2);
                ldsm4(vS + off128(rV + 48, grl), c3);
                {
                    uint32_t p0[2]={c0[0],c0[2]}, p1[2]={c0[1],c0[3]};
                    uint32_t p2[2]={c1[0],c1[2]}, p3[2]={c1[1],c1[3]};
                    uint32_t p4[2]={c2[0],c2[2]}, p5[2]={c2[1],c2[3]};
                    uint32_t p6[2]={c3[0],c3[2]}, p7[2]={c3[1],c3[3]};
                    mma16816(O[0], hiA[jj], p0); mma16816(O[1], hiA[jj], p1);
                    mma16816(O[2], hiA[jj], p2); mma16816(O[3], hiA[jj], p3);
                    mma16816(O[4], hiA[jj], p4); mma16816(O[5], hiA[jj], p5);
                    mma16816(O[6], hiA[jj], p6); mma16816(O[7], hiA[jj], p7);
                }
            }
        }
    }
    // ---- finalize: quad-reduce l, normalize, write packed g_ap ----
#pragma unroll
    for (int rg = 0; rg < 2; rg++) {
        lr[rg] += __shfl_xor_sync(0xffffffffu, lr[rg], 1);
        lr[rg] += __shfl_xor_sync(0xffffffffu, lr[rg], 2);
    }
    const int h = bh & 15, bb = bh >> 4;
#pragma unroll
    for (int rg = 0; rg < 2; rg++) {
        float inv = 1.0f / lr[rg];
        int t = qt * 128 + wm + rowq + rg * 8;
        uint32_t* dst = reinterpret_cast<uint32_t*>(g_ap + ((size_t)bb * T_ + t) * KD);
#pragma unroll
        for (int nt = 0; nt < 8; nt++) {
            int c = nt * 8 + colq;
            float v0 = O[nt][rg*2] * inv;
            float v1 = O[nt][rg*2+1] * inv;
            dst[(h * 64 + c) >> 1] = bfpair(v0, v1);
            dst[(1024 + h * 64 + c) >> 1] = bfpair(bflo(v0), bflo(v1));
        }
    }
}

// ---------------- launch ----------------
extern "C" void kernel_launch(void* const* d_in, const int* in_sizes, int n_in,
                              void* d_out, int out_size)
{
    const float* x  = (const float*)d_in[0];
    const float* Wk = (const float*)d_in[1];
    const float* bk = (const float*)d_in[2];
    const float* Wq = (const float*)d_in[3];
    const float* bq = (const float*)d_in[4];
    const float* Wv = (const float*)d_in[5];
    const float* bv = (const float*)d_in[6];
    const float* Wp = (const float*)d_in[7];
    const float* bp = (const float*)d_in[8];
    float* out = (float*)d_out;

    pack_a_kernel<<<(BT_ * D_) / (4 * 256), 256>>>(x);
    pack_w_kernel<<<dim3(32, 32, 4), 256>>>(Wq, Wk, Wv, Wp);

    cudaFuncSetAttribute(qkv_gemm, cudaFuncAttributeMaxDynamicSharedMemorySize, DSMEM);
    cudaFuncSetAttribute(proj_gemm, cudaFuncAttributeMaxDynamicSharedMemorySize, DSMEM);
    cudaFuncSetAttribute(flash_mma, cudaFuncAttributeMaxDynamicSharedMemorySize, FLASH_SMEM);

    qkv_gemm<<<dim3(8, 64, 3), 256, DSMEM>>>(bq, bk, bv);
    flash_mma<<<dim3(T_ / 128, B_ * NH_), FTHREADS, FLASH_SMEM>>>();
    proj_gemm<<<dim3(8, 64), 256, DSMEM>>>(bp, out);
}

// round 16
// speedup vs baseline: 1.0303x; 1.0131x over previous
#include <cuda_runtime.h>
#include <cuda_bf16.h>
#include <cstdint>
#include <math.h>

#define B_  4
#define T_  2048
#define D_  1024
#define NH_ 16
#define HD_ 64
#define BT_ (B_*T_)
#define KD  2048     // dedup GEMM contraction: [h(1024)|l(1024)]
#define KPH 128      // flash packed head dim: [h(64)|l(64)]
#define LOG2E 1.4426950408889634f

__device__ __align__(128) __nv_bfloat16 g_xp[(size_t)BT_*KD];
__device__ __align__(128) __nv_bfloat16 g_wp[4][(size_t)D_*KD];
__device__ __align__(128) __nv_bfloat16 g_ap[(size_t)BT_*KD];
__device__ __align__(128) __nv_bfloat16 g_qp[(size_t)B_*NH_*T_*KPH];
__device__ __align__(128) __nv_bfloat16 g_kp[(size_t)B_*NH_*T_*KPH];
__device__ __align__(128) __nv_bfloat16 g_vp[(size_t)B_*NH_*HD_*2*T_];

__device__ __forceinline__ uint32_t smem_u32(const void* p) {
    uint32_t a;
    asm("{ .reg .u64 t; cvta.to.shared.u64 t, %1; cvt.u32.u64 %0, t; }" : "=r"(a) : "l"(p));
    return a;
}
__device__ __forceinline__ void cp_async16(uint32_t s, const void* g) {
    asm volatile("cp.async.cg.shared.global [%0], [%1], 16;" :: "r"(s), "l"(g));
}
#define CP_COMMIT() asm volatile("cp.async.commit_group;" ::: "memory")
#define CP_WAIT1()  asm volatile("cp.async.wait_group 1;" ::: "memory")
#define CP_WAIT0()  asm volatile("cp.async.wait_group 0;" ::: "memory")
__device__ __forceinline__ void ldsm4(uint32_t addr, uint32_t r[4]) {
    asm volatile("ldmatrix.sync.aligned.m8n8.x4.shared.b16 {%0,%1,%2,%3}, [%4];"
                 : "=r"(r[0]), "=r"(r[1]), "=r"(r[2]), "=r"(r[3]) : "r"(addr));
}
__device__ __forceinline__ void mma16816(float d[4], const uint32_t a[4], const uint32_t b[2]) {
    asm volatile("mma.sync.aligned.m16n8k16.row.col.f32.bf16.bf16.f32 "
                 "{%0,%1,%2,%3}, {%4,%5,%6,%7}, {%8,%9}, {%0,%1,%2,%3};"
                 : "+f"(d[0]), "+f"(d[1]), "+f"(d[2]), "+f"(d[3])
                 : "r"(a[0]), "r"(a[1]), "r"(a[2]), "r"(a[3]), "r"(b[0]), "r"(b[1]));
}
__device__ __forceinline__ uint32_t bfpair(float x, float y) {
    __nv_bfloat162 t = __floats2bfloat162_rn(x, y);
    return *reinterpret_cast<uint32_t*>(&t);
}
__device__ __forceinline__ float bflo(float x) {
    return x - __bfloat162float(__float2bfloat16(x));
}

// ---------------- pack kernels (dedup [h|l]) ----------------
__global__ __launch_bounds__(256) void pack_a_kernel(const float* __restrict__ X)
{
    int idx = blockIdx.x * 256 + threadIdx.x;
    size_t e = (size_t)idx * 4;
    float4 v = reinterpret_cast<const float4*>(X)[idx];
    int m = (int)(e >> 10), k = (int)(e & 1023);
    uint32_t* dst = reinterpret_cast<uint32_t*>(g_xp + (size_t)m * KD);
    dst[(k >> 1) + 0] = bfpair(v.x, v.y);
    dst[(k >> 1) + 1] = bfpair(v.z, v.w);
    dst[((1024 + k) >> 1) + 0] = bfpair(bflo(v.x), bflo(v.y));
    dst[((1024 + k) >> 1) + 1] = bfpair(bflo(v.z), bflo(v.w));
}

__global__ __launch_bounds__(256) void pack_w_kernel(
    const float* __restrict__ Wq, const float* __restrict__ Wk,
    const float* __restrict__ Wv, const float* __restrict__ Wp)
{
    const float* W = (blockIdx.z == 0) ? Wq : (blockIdx.z == 1) ? Wk :
                     (blockIdx.z == 2) ? Wv : Wp;
    __nv_bfloat16* out = g_wp[blockIdx.z];
    __shared__ float tile[32][33];
    const int tid = threadIdx.x;
    const int n0 = blockIdx.x * 32, k0 = blockIdx.y * 32;
#pragma unroll
    for (int i = 0; i < 4; i++) {
        int kk = (tid >> 5) + i * 8;
        tile[kk][tid & 31] = W[(size_t)(k0 + kk) * D_ + n0 + (tid & 31)];
    }
    __syncthreads();
#pragma unroll
    for (int i = 0; i < 4; i++) {
        int nn = (tid >> 5) + i * 8, kl = tid & 31;
        float v = tile[kl][nn];
        __nv_bfloat16 hi = __float2bfloat16(v);
        size_t base = (size_t)(n0 + nn) * KD + (k0 + kl);
        out[base] = hi;
        out[base + 1024] = __float2bfloat16(v - __bfloat162float(hi));
    }
}

// ---------------- dedup HMMA GEMM (128x128, 32 real k per iter, 3 stages) ----------------
#define DSTAGE 32768
#define DSMEM (3 * DSTAGE)
#define DNIT (D_ / 32)     // 32

__device__ __forceinline__ uint32_t sw_off(int r, int g) {
    return (uint32_t)(r * 64 + ((g ^ ((r >> 1) & 3)) << 4));
}
__device__ __forceinline__ void load_stage2(uint32_t sbuf,
                                            const __nv_bfloat16* __restrict__ A,
                                            const __nv_bfloat16* __restrict__ B, int k)
{
    const int tid = threadIdx.x;
#pragma unroll
    for (int i = 0; i < 8; i++) {
        int ch = tid + i * 256;
        int reg = ch >> 9;
        int r = (ch & 511) >> 2, gc = ch & 3;
        const __nv_bfloat16* base = (reg & 2) ? B : A;
        int off = (reg & 1) ? 1024 : 0;
        cp_async16(sbuf + reg * 8192 + sw_off(r, gc),
                   base + (size_t)r * KD + off + k + gc * 8);
    }
}
__device__ __forceinline__ void mma_blk(float acc[2][8][4], const uint32_t a[2][4],
                                        const uint32_t bp[2][4], int off) {
#pragma unroll
    for (int mt = 0; mt < 2; mt++)
#pragma unroll
        for (int kk = 0; kk < 2; kk++) {
            uint32_t q0[2] = {bp[kk][0], bp[kk][2]};
            uint32_t q1[2] = {bp[kk][1], bp[kk][3]};
            mma16816(acc[mt][off + kk*2 + 0], a[mt], q0);
            mma16816(acc[mt][off + kk*2 + 1], a[mt], q1);
        }
}
__device__ __forceinline__ void gemm_main2(uint32_t smem,
                                           const __nv_bfloat16* __restrict__ A,
                                           const __nv_bfloat16* __restrict__ B,
                                           float acc[2][8][4])
{
    const int tid = threadIdx.x, lane = tid & 31, wid = tid >> 5;
    const int wm = (wid & 3) * 32, wn = (wid >> 2) * 64;
    for (int s = 0; s < 2; s++) { load_stage2(smem + s * DSTAGE, A, B, s * 32); CP_COMMIT(); }
    const int rA = wm + (lane & 15), rB = wn + (lane & 15), kgl = (lane >> 4) & 1;
    int st3 = 0, ld3 = 2;
    for (int ks = 0; ks < DNIT; ks++) {
        CP_WAIT1();
        __syncthreads();
        if (ks + 2 < DNIT) load_stage2(smem + ld3 * DSTAGE, A, B, (ks + 2) * 32);
        CP_COMMIT();
        uint32_t stb = smem + st3 * DSTAGE;
#pragma unroll
        for (int kh = 0; kh < 2; kh++) {
            const int kg = kh * 2 + kgl;
            uint32_t aH[2][4], aL[2][4], bx[2][4], by[2][4];
            ldsm4(stb + sw_off(rA, kg), aH[0]);
            ldsm4(stb + sw_off(rA + 16, kg), aH[1]);
            ldsm4(stb + 16384 + sw_off(rB, kg), bx[0]);
            ldsm4(stb + 16384 + sw_off(rB + 16, kg), bx[1]);
            mma_blk(acc, aH, bx, 0);
            ldsm4(stb + 16384 + sw_off(rB + 32, kg), by[0]);
            ldsm4(stb + 16384 + sw_off(rB + 48, kg), by[1]);
            mma_blk(acc, aH, by, 4);
            ldsm4(stb + 8192 + sw_off(rA, kg), aL[0]);
            ldsm4(stb + 8192 + sw_off(rA + 16, kg), aL[1]);
            mma_blk(acc, aL, bx, 0);
            mma_blk(acc, aL, by, 4);
            ldsm4(stb + 24576 + sw_off(rB, kg), bx[0]);
            ldsm4(stb + 24576 + sw_off(rB + 16, kg), bx[1]);
            mma_blk(acc, aH, bx, 0);
            ldsm4(stb + 24576 + sw_off(rB + 32, kg), by[0]);
            ldsm4(stb + 24576 + sw_off(rB + 48, kg), by[1]);
            mma_blk(acc, aH, by, 4);
        }
        st3 = (st3 == 2) ? 0 : st3 + 1;
        ld3 = (ld3 == 2) ? 0 : ld3 + 1;
    }
}

__global__ __launch_bounds__(256, 2) void qkv_gemm(
    const float* __restrict__ bq, const float* __restrict__ bk, const float* __restrict__ bv)
{
    extern __shared__ __align__(128) char smem[];
    uint32_t sb = smem_u32(smem);
    const int z = blockIdx.z;
    const int m0 = blockIdx.y * 128, n0 = blockIdx.x * 128;
    float acc[2][8][4] = {};
    gemm_main2(sb, g_xp + (size_t)m0 * KD, g_wp[z] + (size_t)n0 * KD, acc);

    const float* bias = (z == 0) ? bq : (z == 1) ? bk : bv;
    const int lane = threadIdx.x & 31, wid = threadIdx.x >> 5;
    const int wm = (wid & 3) * 32, wn = (wid >> 2) * 64;
    const int row_l = lane >> 2, col_l = (lane & 3) * 2;

    if (z <= 1) {
        const int h = (n0 + wn) >> 6;
        __nv_bfloat16* dstp = (z == 0) ? g_qp : g_kp;
        const float qsc = (z == 0) ? LOG2E : 1.0f;   // Q pre-scaled for exp2 softmax
#pragma unroll
        for (int mt = 0; mt < 2; mt++) {
            int mr = m0 + wm + mt * 16 + row_l;
            int bb = mr >> 11, t = mr & (T_ - 1);
            uint32_t* r0p = reinterpret_cast<uint32_t*>(dstp + ((size_t)(bb*NH_+h)*T_ + t) * KPH);
            uint32_t* r8p = r0p + 8 * (KPH / 2);
#pragma unroll
            for (int nt = 0; nt < 8; nt++) {
                int c = nt * 8 + col_l;
                float bxs = bias[n0+wn+c], bys = bias[n0+wn+c+1];
                float v0x = (acc[mt][nt][0]+bxs)*qsc, v0y = (acc[mt][nt][1]+bys)*qsc;
                float v1x = (acc[mt][nt][2]+bxs)*qsc, v1y = (acc[mt][nt][3]+bys)*qsc;
                int ci = nt * 4 + (lane & 3);
                r0p[ci] = bfpair(v0x, v0y); r0p[32+ci] = bfpair(bflo(v0x), bflo(v0y));
                r8p[ci] = bfpair(v1x, v1y); r8p[32+ci] = bfpair(bflo(v1x), bflo(v1y));
            }
        }
    } else {
        // fused V transpose-pack via (dead) stage smem
        float* vt = reinterpret_cast<float*>(smem);
        __syncthreads();
#pragma unroll
        for (int mt = 0; mt < 2; mt++) {
            int rl = wm + mt * 16 + row_l;
#pragma unroll
            for (int nt = 0; nt < 8; nt++) {
                int cl = wn + nt * 8 + col_l;
                float bxs = bias[n0+cl], bys = bias[n0+cl+1];
                vt[rl * 130 + cl]           = acc[mt][nt][0] + bxs;
                vt[rl * 130 + cl + 1]       = acc[mt][nt][1] + bys;
                vt[(rl + 8) * 130 + cl]     = acc[mt][nt][2] + bxs;
                vt[(rl + 8) * 130 + cl + 1] = acc[mt][nt][3] + bys;
            }
        }
        __syncthreads();
        const int tid = threadIdx.x;
        const int c_loc = tid >> 1, half = tid & 1;
        const int h = (n0 + c_loc) >> 6;
        const int c = c_loc & 63;
        const int bb = m0 >> 11, t0 = m0 & (T_ - 1);
        const int bh = bb * NH_ + h;
        const int tl = (t0 >> 6) + half;
        uint32_t outbuf[64];
#pragma unroll
        for (int grp = 0; grp < 2; grp++)
#pragma unroll
            for (int sl2 = 0; sl2 < 16; sl2++) {
                float v0 = vt[(half*64 + grp*32 + 2*sl2)     * 130 + c_loc];
                float v1 = vt[(half*64 + grp*32 + 2*sl2 + 1) * 130 + c_loc];
                outbuf[grp*32 + sl2]      = bfpair(v0, v1);
                outbuf[grp*32 + 16 + sl2] = bfpair(bflo(v0), bflo(v1));
            }
        uint4* dst = reinterpret_cast<uint4*>(
            g_vp + (size_t)bh * HD_ * 2 * T_ + (size_t)c * 2 * T_ + tl * 128);
#pragma unroll
        for (int q = 0; q < 16; q++) dst[q] = reinterpret_cast<uint4*>(outbuf)[q];
    }
}

__global__ __launch_bounds__(256, 2) void proj_gemm(const float* __restrict__ bp, float* __restrict__ outC)
{
    extern __shared__ __align__(128) char smem[];
    uint32_t sb = smem_u32(smem);
    const int m0 = blockIdx.y * 128, n0 = blockIdx.x * 128;
    float acc[2][8][4] = {};
    gemm_main2(sb, g_ap + (size_t)m0 * KD, g_wp[3] + (size_t)n0 * KD, acc);
    const int lane = threadIdx.x & 31, wid = threadIdx.x >> 5;
    const int wm = (wid & 3) * 32, wn = (wid >> 2) * 64;
    const int row_l = lane >> 2, col_l = (lane & 3) * 2;
#pragma unroll
    for (int mt = 0; mt < 2; mt++) {
        int m = m0 + wm + mt * 16 + row_l;
        float* r0p = outC + (size_t)m * D_;
        float* r8p = r0p + 8 * D_;
#pragma unroll
        for (int nt = 0; nt < 8; nt++) {
            int n = n0 + wn + nt * 8 + col_l;
            float2 bi = *reinterpret_cast<const float2*>(&bp[n]);
            float2 v0 = {acc[mt][nt][0]+bi.x, acc[mt][nt][1]+bi.y};
            float2 v1 = {acc[mt][nt][2]+bi.x, acc[mt][nt][3]+bi.y};
            *reinterpret_cast<float2*>(r0p + n) = v0;
            *reinterpret_cast<float2*>(r8p + n) = v1;
        }
    }
}

// ---------------- HMMA flash (R12 structure + local-max exp2 softmax) ----------------
#define FQS 0
#define FKV 32768
#define FPS2 32768
#define FML 65536
#define FLASH_SMEM 98304
#define FTHREADS 512

__device__ __forceinline__ uint32_t off256(int r, int g) {
    return (uint32_t)(r * 256 + ((g ^ (r & 7)) << 4));
}
__device__ __forceinline__ void f_kv(uint32_t sb, const char* gk, const char* gv, int jt, int buf)
{
    const int tid = threadIdx.x;
    uint32_t ks = sb + FKV + buf * 32768;
    uint32_t vs = ks + 16384;
#pragma unroll
    for (int i = 0; i < 2; i++) {
        int ch = tid + i * FTHREADS;      // 0..1023
        int r = ch >> 4, gr = ch & 15;
        cp_async16(ks + off256(r, gr), gk + ((size_t)(jt*64 + r)*KPH + gr*8) * 2);
    }
#pragma unroll
    for (int i = 0; i < 2; i++) {
        int ch = tid + i * FTHREADS;
        int r = ch >> 4, gr = ch & 15;
        cp_async16(vs + off256(r, gr), gv + ((size_t)r*2*T_ + jt*128 + gr*8) * 2);
    }
}

__global__ void __launch_bounds__(FTHREADS, 1) flash_mma()
{
    extern __shared__ __align__(128) char sm[];
    uint32_t sb = smem_u32(sm);
    const int qt = (T_/128 - 1) - blockIdx.x;
    const int bh = blockIdx.y;
    const int tid = threadIdx.x, lane = tid & 31, w = tid >> 5;
    const int wm = (w & 7) * 16;          // M position (16 rows)
    const int g = w >> 3;                 // key half
    const int rowq = lane >> 2, colq = (lane & 3) * 2;
    const int rA = wm + (lane & 15), kgl = (lane >> 4) & 1;

    const char* gq = (const char*)(g_qp + ((size_t)bh*T_ + (size_t)qt*128) * KPH);
    const char* gk = (const char*)(g_kp + (size_t)bh*T_*KPH);
    const char* gv = (const char*)(g_vp + (size_t)bh*HD_*2*T_);

#pragma unroll
    for (int i = 0; i < 4; i++) {
        int ch = tid + i * FTHREADS;      // 0..2047
        int r = ch >> 4, gr = ch & 15;
        cp_async16(sb + FQS + off256(r, gr), gq + ((size_t)r*KPH + gr*8) * 2);
    }
    f_kv(sb, gk, gv, 0, 0);
    CP_COMMIT();

    float O[8][4] = {};
    float mr[2] = {-1e30f, -1e30f};
    float lr[2] = {0.f, 0.f};             // per-thread partial row sums

    const int njt = 2 * qt + 2;
    for (int jt = 0; jt < njt; jt++) {
        const int buf = jt & 1;
        CP_WAIT0();
        __syncthreads();
        if (jt + 1 < njt) { f_kv(sb, gk, gv, jt + 1, buf ^ 1); CP_COMMIT(); }

        const int dk = (jt - 2 * qt) * 64 + g * 32;
        const bool in_diag = (jt >= 2 * qt);
        if (in_diag && dk > wm + 15) continue;        // fully masked

        // ---- S = QK^T (16 rows x 32 keys), 3-term; scores in log2 domain ----
        float s[4][4] = {};
        {
            uint32_t kS = sb + FKV + buf * 32768;
            const int rB = g * 32 + (lane & 15);
#pragma unroll
            for (int j = 0; j < 4; j++) {
                const int grh = 2 * j + kgl, grl = 8 + 2 * j + kgl;
                uint32_t aH[4], aL[4], bH[2][4], bL[2][4];
                ldsm4(sb + FQS + off256(rA, grh), aH);
                ldsm4(kS + off256(rB, grh), bH[0]);
                ldsm4(kS + off256(rB + 16, grh), bH[1]);
#pragma unroll
                for (int kk = 0; kk < 2; kk++) {
                    uint32_t p0[2] = {bH[kk][0], bH[kk][2]};
                    uint32_t p1[2] = {bH[kk][1], bH[kk][3]};
                    mma16816(s[kk*2+0], aH, p0);
                    mma16816(s[kk*2+1], aH, p1);
                }
                ldsm4(sb + FQS + off256(rA, grl), aL);
#pragma unroll
                for (int kk = 0; kk < 2; kk++) {
                    uint32_t p0[2] = {bH[kk][0], bH[kk][2]};
                    uint32_t p1[2] = {bH[kk][1], bH[kk][3]};
                    mma16816(s[kk*2+0], aL, p0);
                    mma16816(s[kk*2+1], aL, p1);
                }
                ldsm4(kS + off256(rB, grl), bL[0]);
                ldsm4(kS + off256(rB + 16, grl), bL[1]);
#pragma unroll
                for (int kk = 0; kk < 2; kk++) {
                    uint32_t p0[2] = {bL[kk][0], bL[kk][2]};
                    uint32_t p1[2] = {bL[kk][1], bL[kk][3]};
                    mma16816(s[kk*2+0], aH, p0);
                    mma16816(s[kk*2+1], aH, p1);
                }
            }
        }
        // mask only when the diagonal crosses this 16x32 tile
        if (in_diag && dk + 31 > wm) {
            const int rg0 = wm + rowq;
            const int cg0 = dk + colq;
#pragma unroll
            for (int nt = 0; nt < 4; nt++)
#pragma unroll
                for (int e = 0; e < 4; e++)
                    if (cg0 + nt * 8 + (e & 1) > rg0 + (e >> 1) * 8)
                        s[nt][e] = -1e30f;
        }
        // ---- local-max softmax: exps vs thread-local max (safe, <=1), parallel w/ shfl ----
        float psc[2], rsc[2];
#pragma unroll
        for (int rg = 0; rg < 2; rg++) {
            float tm = -1e30f;
#pragma unroll
            for (int nt = 0; nt < 4; nt++)
                tm = fmaxf(tm, fmaxf(s[nt][rg*2], s[nt][rg*2+1]));
            // exps start now (depend only on tm); shfl reduction proceeds in parallel
            float rs = 0.0f;
#pragma unroll
            for (int nt = 0; nt < 4; nt++) {
                float p0 = exp2f(s[nt][rg*2]   - tm);
                float p1 = exp2f(s[nt][rg*2+1] - tm);
                s[nt][rg*2] = p0; s[nt][rg*2+1] = p1;
                rs += p0 + p1;
            }
            float tw = fmaxf(tm, __shfl_xor_sync(0xffffffffu, tm, 1));
            tw = fmaxf(tw, __shfl_xor_sync(0xffffffffu, tw, 2));
            float mn = fmaxf(mr[rg], tw);
            float resc = (tm < -1e29f) ? 0.0f : exp2f(tm - mn);   // masked row-group -> 0
            float sc = exp2f(mr[rg] - mn);                         // sentinel underflows to 0
            lr[rg] = lr[rg] * sc + rs * resc;
            mr[rg] = mn;
            psc[rg] = sc;
            rsc[rg] = resc;
        }
#pragma unroll
        for (int ot = 0; ot < 8; ot++) {
            O[ot][0] *= psc[0]; O[ot][1] *= psc[0];
            O[ot][2] *= psc[1]; O[ot][3] *= psc[1];
        }
        // ---- P fragments (p rescaled local->global domain) ----
        uint32_t hiA[2][4], loA[2][4];
#pragma unroll
        for (int j2 = 0; j2 < 2; j2++) {
            float a0 = s[2*j2][0]   * rsc[0], a1 = s[2*j2][1]   * rsc[0];
            float a2 = s[2*j2][2]   * rsc[1], a3 = s[2*j2][3]   * rsc[1];
            float b0 = s[2*j2+1][0] * rsc[0], b1 = s[2*j2+1][1] * rsc[0];
            float b2 = s[2*j2+1][2] * rsc[1], b3 = s[2*j2+1][3] * rsc[1];
            hiA[j2][0] = bfpair(a0, a1);
            hiA[j2][1] = bfpair(a2, a3);
            hiA[j2][2] = bfpair(b0, b1);
            hiA[j2][3] = bfpair(b2, b3);
            loA[j2][0] = bfpair(bflo(a0), bflo(a1));
            loA[j2][1] = bfpair(bflo(a2), bflo(a3));
            loA[j2][2] = bfpair(bflo(b0), bflo(b1));
            loA[j2][3] = bfpair(bflo(b2), bflo(b3));
        }
        // ---- O += P·V (3-term) ----
        {
            uint32_t vS = sb + FKV + buf * 32768 + 16384;
            const int rV = lane & 15;
#pragma unroll
            for (int jj = 0; jj < 2; jj++) {
                const int grh = 8 * g + 2 * jj + kgl;
                const int grl = grh + 4;
                uint32_t bh4[4][4], bl4[4][4];
#pragma unroll
                for (int ng = 0; ng < 4; ng++) ldsm4(vS + off256(rV + 16*ng, grh), bh4[ng]);
#pragma unroll
                for (int ng = 0; ng < 4; ng++) {
                    uint32_t p0[2] = {bh4[ng][0], bh4[ng][2]};
                    uint32_t p1[2] = {bh4[ng][1], bh4[ng][3]};
                    mma16816(O[ng*2+0], hiA[jj], p0);
                    mma16816(O[ng*2+1], hiA[jj], p1);
                }
#pragma unroll
                for (int ng = 0; ng < 4; ng++) ldsm4(vS + off256(rV + 16*ng, grl), bl4[ng]);
#pragma unroll
                for (int ng = 0; ng < 4; ng++) {
                    uint32_t p0[2] = {bl4[ng][0], bl4[ng][2]};
                    uint32_t p1[2] = {bl4[ng][1], bl4[ng][3]};
                    mma16816(O[ng*2+0], hiA[jj], p0);
                    mma16816(O[ng*2+1], hiA[jj], p1);
                }
#pragma unroll
                for (int ng = 0; ng < 4; ng++) {
                    uint32_t p0[2] = {bh4[ng][0], bh4[ng][2]};
                    uint32_t p1[2] = {bh4[ng][1], bh4[ng][3]};
                    mma16816(O[ng*2+0], loA[jj], p0);
                    mma16816(O[ng*2+1], loA[jj], p1);
                }
            }
        }
    }
    // ---- finalize l: quad reduction (deferred from the loop) ----
#pragma unroll
    for (int rg = 0; rg < 2; rg++) {
        lr[rg] += __shfl_xor_sync(0xffffffffu, lr[rg], 1);
        lr[rg] += __shfl_xor_sync(0xffffffffu, lr[rg], 2);
    }
    // ---- merge halves (reuses dead KV smem) ----
    __syncthreads();
    if (g == 1) {
#pragma unroll
        for (int rg = 0; rg < 2; rg++) {
            int r = wm + rowq + rg * 8;
            if ((lane & 3) == 0)
                *reinterpret_cast<float2*>(sm + FML + r * 8) = make_float2(mr[rg], lr[rg]);
#pragma unroll
            for (int nt = 0; nt < 8; nt++) {
                int c = nt * 8 + colq;
                *reinterpret_cast<float2*>(sm + FPS2 + (r * 64 + c) * 4) =
                    make_float2(O[nt][rg*2], O[nt][rg*2+1]);
            }
        }
    }
    __syncthreads();
    if (g == 0) {
        const int h = bh & 15, bb = bh >> 4;
#pragma unroll
        for (int rg = 0; rg < 2; rg++) {
            int rl = wm + rowq + rg * 8;
            float2 ml1 = *reinterpret_cast<float2*>(sm + FML + rl * 8);
            float M = fmaxf(mr[rg], ml1.x);
            float sc0 = exp2f(mr[rg] - M), sc1 = exp2f(ml1.x - M);
            float inv = 1.0f / (lr[rg] * sc0 + ml1.y * sc1);
            int t = qt * 128 + rl;
            uint32_t* dst = reinterpret_cast<uint32_t*>(g_ap + ((size_t)bb * T_ + t) * KD);
#pragma unroll
            for (int nt = 0; nt < 8; nt++) {
                int c = nt * 8 + colq;
                float2 o1 = *reinterpret_cast<float2*>(sm + FPS2 + (rl * 64 + c) * 4);
                float v0 = (O[nt][rg*2] * sc0 + o1.x * sc1) * inv;
                float v1 = (O[nt][rg*2+1] * sc0 + o1.y * sc1) * inv;
                dst[(h * 64 + c) >> 1] = bfpair(v0, v1);
                dst[(1024 + h * 64 + c) >> 1] = bfpair(bflo(v0), bflo(v1));
            }
        }
    }
}

// ---------------- launch ----------------
extern "C" void kernel_launch(void* const* d_in, const int* in_sizes, int n_in,
                              void* d_out, int out_size)
{
    const float* x  = (const float*)d_in[0];
    const float* Wk = (const float*)d_in[1];
    const float* bk = (const float*)d_in[2];
    const float* Wq = (const float*)d_in[3];
    const float* bq = (const float*)d_in[4];
    const float* Wv = (const float*)d_in[5];
    const float* bv = (const float*)d_in[6];
    const float* Wp = (const float*)d_in[7];
    const float* bp = (const float*)d_in[8];
    float* out = (float*)d_out;

    pack_a_kernel<<<(BT_ * D_) / (4 * 256), 256>>>(x);
    pack_w_kernel<<<dim3(32, 32, 4), 256>>>(Wq, Wk, Wv, Wp);

    cudaFuncSetAttribute(qkv_gemm, cudaFuncAttributeMaxDynamicSharedMemorySize, DSMEM);
    cudaFuncSetAttribute(proj_gemm, cudaFuncAttributeMaxDynamicSharedMemorySize, DSMEM);
    cudaFuncSetAttribute(flash_mma, cudaFuncAttributeMaxDynamicSharedMemorySize, FLASH_SMEM);

    qkv_gemm<<<dim3(8, 64, 3), 256, DSMEM>>>(bq, bk, bv);
    flash_mma<<<dim3(T_ / 128, B_ * NH_), FTHREADS, FLASH_SMEM>>>();
    proj_gemm<<<dim3(8, 64), 256, DSMEM>>>(bp, out);
}

// round 17
// speedup vs baseline: 1.1467x; 1.1129x over previous
#include <cuda_runtime.h>
#include <cuda_bf16.h>
#include <cuda_fp16.h>
#include <cstdint>
#include <math.h>

#define B_  4
#define T_  2048
#define D_  1024
#define NH_ 16
#define HD_ 64
#define BT_ (B_*T_)
#define KD  2048     // qkv dedup contraction: [h(1024)|l(1024)] bf16
#define KPH 128      // flash packed head dim: [h(64)|l(64)]
#define LOG2E 1.4426950408889634f

__device__ __align__(128) __nv_bfloat16 g_xp[(size_t)BT_*KD];
__device__ __align__(128) __nv_bfloat16 g_wp[4][(size_t)D_*KD];   // [3] holds fp16 Wp_h (1024/row)
__device__ __align__(128) __nv_bfloat16 g_ap[(size_t)BT_*KD];     // fp16 ctx [h|l]
__device__ __align__(128) __nv_bfloat16 g_qp[(size_t)B_*NH_*T_*KPH];
__device__ __align__(128) __nv_bfloat16 g_kp[(size_t)B_*NH_*T_*KPH];
__device__ __align__(128) __nv_bfloat16 g_vp[(size_t)B_*NH_*HD_*2*T_];  // fp16 [Vh|Vl]

__device__ __forceinline__ uint32_t smem_u32(const void* p) {
    uint32_t a;
    asm("{ .reg .u64 t; cvta.to.shared.u64 t, %1; cvt.u32.u64 %0, t; }" : "=r"(a) : "l"(p));
    return a;
}
__device__ __forceinline__ void cp_async16(uint32_t s, const void* g) {
    asm volatile("cp.async.cg.shared.global [%0], [%1], 16;" :: "r"(s), "l"(g));
}
#define CP_COMMIT() asm volatile("cp.async.commit_group;" ::: "memory")
#define CP_WAIT1()  asm volatile("cp.async.wait_group 1;" ::: "memory")
#define CP_WAIT0()  asm volatile("cp.async.wait_group 0;" ::: "memory")
__device__ __forceinline__ void ldsm4(uint32_t addr, uint32_t r[4]) {
    asm volatile("ldmatrix.sync.aligned.m8n8.x4.shared.b16 {%0,%1,%2,%3}, [%4];"
                 : "=r"(r[0]), "=r"(r[1]), "=r"(r[2]), "=r"(r[3]) : "r"(addr));
}
__device__ __forceinline__ void mma16816(float d[4], const uint32_t a[4], const uint32_t b[2]) {
    asm volatile("mma.sync.aligned.m16n8k16.row.col.f32.bf16.bf16.f32 "
                 "{%0,%1,%2,%3}, {%4,%5,%6,%7}, {%8,%9}, {%0,%1,%2,%3};"
                 : "+f"(d[0]), "+f"(d[1]), "+f"(d[2]), "+f"(d[3])
                 : "r"(a[0]), "r"(a[1]), "r"(a[2]), "r"(a[3]), "r"(b[0]), "r"(b[1]));
}
__device__ __forceinline__ void mma16816h(float d[4], const uint32_t a[4], const uint32_t b[2]) {
    asm volatile("mma.sync.aligned.m16n8k16.row.col.f32.f16.f16.f32 "
                 "{%0,%1,%2,%3}, {%4,%5,%6,%7}, {%8,%9}, {%0,%1,%2,%3};"
                 : "+f"(d[0]), "+f"(d[1]), "+f"(d[2]), "+f"(d[3])
                 : "r"(a[0]), "r"(a[1]), "r"(a[2]), "r"(a[3]), "r"(b[0]), "r"(b[1]));
}
__device__ __forceinline__ uint32_t bfpair(float x, float y) {
    __nv_bfloat162 t = __floats2bfloat162_rn(x, y);
    return *reinterpret_cast<uint32_t*>(&t);
}
__device__ __forceinline__ float bflo(float x) {
    return x - __bfloat162float(__float2bfloat16(x));
}
__device__ __forceinline__ uint32_t hfpair(float x, float y) {
    __half2 t = __floats2half2_rn(x, y);
    return *reinterpret_cast<uint32_t*>(&t);
}
__device__ __forceinline__ float hflo(float x) {
    return x - __half2float(__float2half_rn(x));
}

// ---------------- pack kernels ----------------
__global__ __launch_bounds__(256) void pack_a_kernel(const float* __restrict__ X)
{
    int idx = blockIdx.x * 256 + threadIdx.x;
    size_t e = (size_t)idx * 4;
    float4 v = reinterpret_cast<const float4*>(X)[idx];
    int m = (int)(e >> 10), k = (int)(e & 1023);
    uint32_t* dst = reinterpret_cast<uint32_t*>(g_xp + (size_t)m * KD);
    dst[(k >> 1) + 0] = bfpair(v.x, v.y);
    dst[(k >> 1) + 1] = bfpair(v.z, v.w);
    dst[((1024 + k) >> 1) + 0] = bfpair(bflo(v.x), bflo(v.y));
    dst[((1024 + k) >> 1) + 1] = bfpair(bflo(v.z), bflo(v.w));
}

__global__ __launch_bounds__(256) void pack_w_kernel(
    const float* __restrict__ Wq, const float* __restrict__ Wk,
    const float* __restrict__ Wv, const float* __restrict__ Wp)
{
    const float* W = (blockIdx.z == 0) ? Wq : (blockIdx.z == 1) ? Wk :
                     (blockIdx.z == 2) ? Wv : Wp;
    __shared__ float tile[32][33];
    const int tid = threadIdx.x;
    const int n0 = blockIdx.x * 32, k0 = blockIdx.y * 32;
#pragma unroll
    for (int i = 0; i < 4; i++) {
        int kk = (tid >> 5) + i * 8;
        tile[kk][tid & 31] = W[(size_t)(k0 + kk) * D_ + n0 + (tid & 31)];
    }
    __syncthreads();
#pragma unroll
    for (int i = 0; i < 4; i++) {
        int nn = (tid >> 5) + i * 8, kl = tid & 31;
        float v = tile[kl][nn];
        if (blockIdx.z == 3) {   // Wp: single fp16, row stride 1024
            __half* out = reinterpret_cast<__half*>(g_wp[3]);
            out[(size_t)(n0 + nn) * 1024 + (k0 + kl)] = __float2half_rn(v);
        } else {
            __nv_bfloat16* out = g_wp[blockIdx.z];
            __nv_bfloat16 hi = __float2bfloat16(v);
            size_t base = (size_t)(n0 + nn) * KD + (k0 + kl);
            out[base] = hi;
            out[base + 1024] = __float2bfloat16(v - __bfloat162float(hi));
        }
    }
}

// ---------------- dedup bf16 HMMA GEMM for QKV (128x128, 32 real k/iter, 3 stages) ----------------
#define DSTAGE 32768
#define DSMEM (3 * DSTAGE)
#define DNIT (D_ / 32)     // 32

__device__ __forceinline__ uint32_t sw_off(int r, int g) {
    return (uint32_t)(r * 64 + ((g ^ ((r >> 1) & 3)) << 4));
}
__device__ __forceinline__ void load_stage2(uint32_t sbuf,
                                            const __nv_bfloat16* __restrict__ A,
                                            const __nv_bfloat16* __restrict__ B, int k)
{
    const int tid = threadIdx.x;
#pragma unroll
    for (int i = 0; i < 8; i++) {
        int ch = tid + i * 256;
        int reg = ch >> 9;
        int r = (ch & 511) >> 2, gc = ch & 3;
        const __nv_bfloat16* base = (reg & 2) ? B : A;
        int off = (reg & 1) ? 1024 : 0;
        cp_async16(sbuf + reg * 8192 + sw_off(r, gc),
                   base + (size_t)r * KD + off + k + gc * 8);
    }
}
__device__ __forceinline__ void mma_blk(float acc[2][8][4], const uint32_t a[2][4],
                                        const uint32_t bp[2][4], int off) {
#pragma unroll
    for (int mt = 0; mt < 2; mt++)
#pragma unroll
        for (int kk = 0; kk < 2; kk++) {
            uint32_t q0[2] = {bp[kk][0], bp[kk][2]};
            uint32_t q1[2] = {bp[kk][1], bp[kk][3]};
            mma16816(acc[mt][off + kk*2 + 0], a[mt], q0);
            mma16816(acc[mt][off + kk*2 + 1], a[mt], q1);
        }
}
__device__ __forceinline__ void gemm_main2(uint32_t smem,
                                           const __nv_bfloat16* __restrict__ A,
                                           const __nv_bfloat16* __restrict__ B,
                                           float acc[2][8][4])
{
    const int tid = threadIdx.x, lane = tid & 31, wid = tid >> 5;
    const int wm = (wid & 3) * 32, wn = (wid >> 2) * 64;
    for (int s = 0; s < 2; s++) { load_stage2(smem + s * DSTAGE, A, B, s * 32); CP_COMMIT(); }
    const int rA = wm + (lane & 15), rB = wn + (lane & 15), kgl = (lane >> 4) & 1;
    int st3 = 0, ld3 = 2;
    for (int ks = 0; ks < DNIT; ks++) {
        CP_WAIT1();
        __syncthreads();
        if (ks + 2 < DNIT) load_stage2(smem + ld3 * DSTAGE, A, B, (ks + 2) * 32);
        CP_COMMIT();
        uint32_t stb = smem + st3 * DSTAGE;
#pragma unroll
        for (int kh = 0; kh < 2; kh++) {
            const int kg = kh * 2 + kgl;
            uint32_t aH[2][4], aL[2][4], bx[2][4], by[2][4];
            ldsm4(stb + sw_off(rA, kg), aH[0]);
            ldsm4(stb + sw_off(rA + 16, kg), aH[1]);
            ldsm4(stb + 16384 + sw_off(rB, kg), bx[0]);
            ldsm4(stb + 16384 + sw_off(rB + 16, kg), bx[1]);
            mma_blk(acc, aH, bx, 0);
            ldsm4(stb + 16384 + sw_off(rB + 32, kg), by[0]);
            ldsm4(stb + 16384 + sw_off(rB + 48, kg), by[1]);
            mma_blk(acc, aH, by, 4);
            ldsm4(stb + 8192 + sw_off(rA, kg), aL[0]);
            ldsm4(stb + 8192 + sw_off(rA + 16, kg), aL[1]);
            mma_blk(acc, aL, bx, 0);
            mma_blk(acc, aL, by, 4);
            ldsm4(stb + 24576 + sw_off(rB, kg), bx[0]);
            ldsm4(stb + 24576 + sw_off(rB + 16, kg), bx[1]);
            mma_blk(acc, aH, bx, 0);
            ldsm4(stb + 24576 + sw_off(rB + 32, kg), by[0]);
            ldsm4(stb + 24576 + sw_off(rB + 48, kg), by[1]);
            mma_blk(acc, aH, by, 4);
        }
        st3 = (st3 == 2) ? 0 : st3 + 1;
        ld3 = (ld3 == 2) ? 0 : ld3 + 1;
    }
}

__global__ __launch_bounds__(256, 2) void qkv_gemm(
    const float* __restrict__ bq, const float* __restrict__ bk, const float* __restrict__ bv)
{
    extern __shared__ __align__(128) char smem[];
    uint32_t sb = smem_u32(smem);
    const int z = blockIdx.z;
    const int m0 = blockIdx.y * 128, n0 = blockIdx.x * 128;
    float acc[2][8][4] = {};
    gemm_main2(sb, g_xp + (size_t)m0 * KD, g_wp[z] + (size_t)n0 * KD, acc);

    const float* bias = (z == 0) ? bq : (z == 1) ? bk : bv;
    const int lane = threadIdx.x & 31, wid = threadIdx.x >> 5;
    const int wm = (wid & 3) * 32, wn = (wid >> 2) * 64;
    const int row_l = lane >> 2, col_l = (lane & 3) * 2;

    if (z <= 1) {
        const int h = (n0 + wn) >> 6;
        __nv_bfloat16* dstp = (z == 0) ? g_qp : g_kp;
        const float qsc = (z == 0) ? LOG2E : 1.0f;
#pragma unroll
        for (int mt = 0; mt < 2; mt++) {
            int mr = m0 + wm + mt * 16 + row_l;
            int bb = mr >> 11, t = mr & (T_ - 1);
            uint32_t* r0p = reinterpret_cast<uint32_t*>(dstp + ((size_t)(bb*NH_+h)*T_ + t) * KPH);
            uint32_t* r8p = r0p + 8 * (KPH / 2);
#pragma unroll
            for (int nt = 0; nt < 8; nt++) {
                int c = nt * 8 + col_l;
                float bxs = bias[n0+wn+c], bys = bias[n0+wn+c+1];
                float v0x = (acc[mt][nt][0]+bxs)*qsc, v0y = (acc[mt][nt][1]+bys)*qsc;
                float v1x = (acc[mt][nt][2]+bxs)*qsc, v1y = (acc[mt][nt][3]+bys)*qsc;
                int ci = nt * 4 + (lane & 3);
                r0p[ci] = bfpair(v0x, v0y); r0p[32+ci] = bfpair(bflo(v0x), bflo(v0y));
                r8p[ci] = bfpair(v1x, v1y); r8p[32+ci] = bfpair(bflo(v1x), bflo(v1y));
            }
        }
    } else {
        // fused V transpose-pack -> fp16 [Vh|Vl]
        float* vt = reinterpret_cast<float*>(smem);
        __syncthreads();
#pragma unroll
        for (int mt = 0; mt < 2; mt++) {
            int rl = wm + mt * 16 + row_l;
#pragma unroll
            for (int nt = 0; nt < 8; nt++) {
                int cl = wn + nt * 8 + col_l;
                float bxs = bias[n0+cl], bys = bias[n0+cl+1];
                vt[rl * 130 + cl]           = acc[mt][nt][0] + bxs;
                vt[rl * 130 + cl + 1]       = acc[mt][nt][1] + bys;
                vt[(rl + 8) * 130 + cl]     = acc[mt][nt][2] + bxs;
                vt[(rl + 8) * 130 + cl + 1] = acc[mt][nt][3] + bys;
            }
        }
        __syncthreads();
        const int tid = threadIdx.x;
        const int c_loc = tid >> 1, half = tid & 1;
        const int h = (n0 + c_loc) >> 6;
        const int c = c_loc & 63;
        const int bb = m0 >> 11, t0 = m0 & (T_ - 1);
        const int bh = bb * NH_ + h;
        const int tl = (t0 >> 6) + half;
        uint32_t outbuf[64];
#pragma unroll
        for (int grp = 0; grp < 2; grp++)
#pragma unroll
            for (int sl2 = 0; sl2 < 16; sl2++) {
                float v0 = vt[(half*64 + grp*32 + 2*sl2)     * 130 + c_loc];
                float v1 = vt[(half*64 + grp*32 + 2*sl2 + 1) * 130 + c_loc];
                outbuf[grp*32 + sl2]      = hfpair(v0, v1);
                outbuf[grp*32 + 16 + sl2] = hfpair(hflo(v0), hflo(v1));
            }
        uint4* dst = reinterpret_cast<uint4*>(
            g_vp + (size_t)bh * HD_ * 2 * T_ + (size_t)c * 2 * T_ + tl * 128);
#pragma unroll
        for (int q = 0; q < 16; q++) dst[q] = reinterpret_cast<uint4*>(outbuf)[q];
    }
}

// ---------------- proj GEMM: fp16 2-term (Ah·B + Al·B), K=1024 ----------------
// stage 24KB: Ah@0, Al@8K, B@16K ; 3 stages = 72KB
#define PSTAGE 24576
#define PSMEM (3 * PSTAGE)

__device__ __forceinline__ void load_stageP(uint32_t sbuf,
                                            const __half* __restrict__ A,
                                            const __half* __restrict__ B, int k)
{
    const int tid = threadIdx.x;
#pragma unroll
    for (int i = 0; i < 6; i++) {
        int ch = tid + i * 256;          // 0..1535
        int reg = ch / 512;              // 0=Ah 1=Al 2=B
        int r = (ch & 511) >> 2, gc = ch & 3;
        const void* src;
        if (reg == 0)      src = A + (size_t)r * KD + k + gc * 8;
        else if (reg == 1) src = A + (size_t)r * KD + 1024 + k + gc * 8;
        else               src = B + (size_t)r * 1024 + k + gc * 8;
        cp_async16(sbuf + reg * 8192 + sw_off(r, gc), src);
    }
}

__global__ __launch_bounds__(256, 2) void proj_gemm(const float* __restrict__ bp, float* __restrict__ outC)
{
    extern __shared__ __align__(128) char smem[];
    uint32_t sb = smem_u32(smem);
    const int m0 = blockIdx.y * 128, n0 = blockIdx.x * 128;
    const __half* A = reinterpret_cast<const __half*>(g_ap) + (size_t)m0 * KD;
    const __half* Bp = reinterpret_cast<const __half*>(g_wp[3]) + (size_t)n0 * 1024;

    float acc[2][8][4] = {};
    const int tid = threadIdx.x, lane = tid & 31, wid = tid >> 5;
    const int wm = (wid & 3) * 32, wn = (wid >> 2) * 64;
    for (int s = 0; s < 2; s++) { load_stageP(sb + s * PSTAGE, A, Bp, s * 32); CP_COMMIT(); }
    const int rA = wm + (lane & 15), rB = wn + (lane & 15), kgl = (lane >> 4) & 1;
    int st3 = 0, ld3 = 2;
    for (int ks = 0; ks < DNIT; ks++) {
        CP_WAIT1();
        __syncthreads();
        if (ks + 2 < DNIT) load_stageP(sb + ld3 * PSTAGE, A, Bp, (ks + 2) * 32);
        CP_COMMIT();
        uint32_t stb = sb + st3 * PSTAGE;
#pragma unroll
        for (int kh = 0; kh < 2; kh++) {
            const int kg = kh * 2 + kgl;
            uint32_t aH[2][4], aL[2][4], bx[2][4], by[2][4];
            ldsm4(stb + sw_off(rA, kg), aH[0]);
            ldsm4(stb + sw_off(rA + 16, kg), aH[1]);
            ldsm4(stb + 16384 + sw_off(rB, kg), bx[0]);
            ldsm4(stb + 16384 + sw_off(rB + 16, kg), bx[1]);
            ldsm4(stb + 16384 + sw_off(rB + 32, kg), by[0]);
            ldsm4(stb + 16384 + sw_off(rB + 48, kg), by[1]);
#pragma unroll
            for (int mt = 0; mt < 2; mt++)
#pragma unroll
                for (int kk = 0; kk < 2; kk++) {
                    uint32_t q0[2] = {bx[kk][0], bx[kk][2]};
                    uint32_t q1[2] = {bx[kk][1], bx[kk][3]};
                    uint32_t q2[2] = {by[kk][0], by[kk][2]};
                    uint32_t q3[2] = {by[kk][1], by[kk][3]};
                    mma16816h(acc[mt][kk*2+0], aH[mt], q0);
                    mma16816h(acc[mt][kk*2+1], aH[mt], q1);
                    mma16816h(acc[mt][4+kk*2+0], aH[mt], q2);
                    mma16816h(acc[mt][4+kk*2+1], aH[mt], q3);
                }
            ldsm4(stb + 8192 + sw_off(rA, kg), aL[0]);
            ldsm4(stb + 8192 + sw_off(rA + 16, kg), aL[1]);
#pragma unroll
            for (int mt = 0; mt < 2; mt++)
#pragma unroll
                for (int kk = 0; kk < 2; kk++) {
                    uint32_t q0[2] = {bx[kk][0], bx[kk][2]};
                    uint32_t q1[2] = {bx[kk][1], bx[kk][3]};
                    uint32_t q2[2] = {by[kk][0], by[kk][2]};
                    uint32_t q3[2] = {by[kk][1], by[kk][3]};
                    mma16816h(acc[mt][kk*2+0], aL[mt], q0);
                    mma16816h(acc[mt][kk*2+1], aL[mt], q1);
                    mma16816h(acc[mt][4+kk*2+0], aL[mt], q2);
                    mma16816h(acc[mt][4+kk*2+1], aL[mt], q3);
                }
        }
        st3 = (st3 == 2) ? 0 : st3 + 1;
        ld3 = (ld3 == 2) ? 0 : ld3 + 1;
    }
    const int row_l = lane >> 2, col_l = (lane & 3) * 2;
#pragma unroll
    for (int mt = 0; mt < 2; mt++) {
        int m = m0 + wm + mt * 16 + row_l;
        float* r0p = outC + (size_t)m * D_;
        float* r8p = r0p + 8 * D_;
#pragma unroll
        for (int nt = 0; nt < 8; nt++) {
            int n = n0 + wn + nt * 8 + col_l;
            float2 bi = *reinterpret_cast<const float2*>(&bp[n]);
            float2 v0 = {acc[mt][nt][0]+bi.x, acc[mt][nt][1]+bi.y};
            float2 v1 = {acc[mt][nt][2]+bi.x, acc[mt][nt][3]+bi.y};
            *reinterpret_cast<float2*>(r0p + n) = v0;
            *reinterpret_cast<float2*>(r8p + n) = v1;
        }
    }
}

// ---------------- HMMA flash (R16 + fp16 2-term PV) ----------------
#define FQS 0
#define FKV 32768
#define FPS2 32768
#define FML 65536
#define FLASH_SMEM 98304
#define FTHREADS 512

__device__ __forceinline__ uint32_t off256(int r, int g) {
    return (uint32_t)(r * 256 + ((g ^ (r & 7)) << 4));
}
__device__ __forceinline__ void f_kv(uint32_t sb, const char* gk, const char* gv, int jt, int buf)
{
    const int tid = threadIdx.x;
    uint32_t ks = sb + FKV + buf * 32768;
    uint32_t vs = ks + 16384;
#pragma unroll
    for (int i = 0; i < 2; i++) {
        int ch = tid + i * FTHREADS;
        int r = ch >> 4, gr = ch & 15;
        cp_async16(ks + off256(r, gr), gk + ((size_t)(jt*64 + r)*KPH + gr*8) * 2);
    }
#pragma unroll
    for (int i = 0; i < 2; i++) {
        int ch = tid + i * FTHREADS;
        int r = ch >> 4, gr = ch & 15;
        cp_async16(vs + off256(r, gr), gv + ((size_t)r*2*T_ + jt*128 + gr*8) * 2);
    }
}

__global__ void __launch_bounds__(FTHREADS, 1) flash_mma()
{
    extern __shared__ __align__(128) char sm[];
    uint32_t sb = smem_u32(sm);
    const int qt = (T_/128 - 1) - blockIdx.x;
    const int bh = blockIdx.y;
    const int tid = threadIdx.x, lane = tid & 31, w = tid >> 5;
    const int wm = (w & 7) * 16;
    const int g = w >> 3;
    const int rowq = lane >> 2, colq = (lane & 3) * 2;
    const int rA = wm + (lane & 15), kgl = (lane >> 4) & 1;

    const char* gq = (const char*)(g_qp + ((size_t)bh*T_ + (size_t)qt*128) * KPH);
    const char* gk = (const char*)(g_kp + (size_t)bh*T_*KPH);
    const char* gv = (const char*)(g_vp + (size_t)bh*HD_*2*T_);

#pragma unroll
    for (int i = 0; i < 4; i++) {
        int ch = tid + i * FTHREADS;
        int r = ch >> 4, gr = ch & 15;
        cp_async16(sb + FQS + off256(r, gr), gq + ((size_t)r*KPH + gr*8) * 2);
    }
    f_kv(sb, gk, gv, 0, 0);
    CP_COMMIT();

    float O[8][4] = {};
    float mr[2] = {-1e30f, -1e30f};
    float lr[2] = {0.f, 0.f};

    const int njt = 2 * qt + 2;
    for (int jt = 0; jt < njt; jt++) {
        const int buf = jt & 1;
        CP_WAIT0();
        __syncthreads();
        if (jt + 1 < njt) { f_kv(sb, gk, gv, jt + 1, buf ^ 1); CP_COMMIT(); }

        const int dk = (jt - 2 * qt) * 64 + g * 32;
        const bool in_diag = (jt >= 2 * qt);
        if (in_diag && dk > wm + 15) continue;

        // ---- S = QK^T (bf16 3-term), log2 domain ----
        float s[4][4] = {};
        {
            uint32_t kS = sb + FKV + buf * 32768;
            const int rB = g * 32 + (lane & 15);
#pragma unroll
            for (int j = 0; j < 4; j++) {
                const int grh = 2 * j + kgl, grl = 8 + 2 * j + kgl;
                uint32_t aH[4], aL[4], bH[2][4], bL[2][4];
                ldsm4(sb + FQS + off256(rA, grh), aH);
                ldsm4(kS + off256(rB, grh), bH[0]);
                ldsm4(kS + off256(rB + 16, grh), bH[1]);
#pragma unroll
                for (int kk = 0; kk < 2; kk++) {
                    uint32_t p0[2] = {bH[kk][0], bH[kk][2]};
                    uint32_t p1[2] = {bH[kk][1], bH[kk][3]};
                    mma16816(s[kk*2+0], aH, p0);
                    mma16816(s[kk*2+1], aH, p1);
                }
                ldsm4(sb + FQS + off256(rA, grl), aL);
#pragma unroll
                for (int kk = 0; kk < 2; kk++) {
                    uint32_t p0[2] = {bH[kk][0], bH[kk][2]};
                    uint32_t p1[2] = {bH[kk][1], bH[kk][3]};
                    mma16816(s[kk*2+0], aL, p0);
                    mma16816(s[kk*2+1], aL, p1);
                }
                ldsm4(kS + off256(rB, grl), bL[0]);
                ldsm4(kS + off256(rB + 16, grl), bL[1]);
#pragma unroll
                for (int kk = 0; kk < 2; kk++) {
                    uint32_t p0[2] = {bL[kk][0], bL[kk][2]};
                    uint32_t p1[2] = {bL[kk][1], bL[kk][3]};
                    mma16816(s[kk*2+0], aH, p0);
                    mma16816(s[kk*2+1], aH, p1);
                }
            }
        }
        if (in_diag && dk + 31 > wm) {
            const int rg0 = wm + rowq;
            const int cg0 = dk + colq;
#pragma unroll
            for (int nt = 0; nt < 4; nt++)
#pragma unroll
                for (int e = 0; e < 4; e++)
                    if (cg0 + nt * 8 + (e & 1) > rg0 + (e >> 1) * 8)
                        s[nt][e] = -1e30f;
        }
        // ---- local-max exp2 softmax ----
        float psc[2], rsc[2];
#pragma unroll
        for (int rg = 0; rg < 2; rg++) {
            float tm = -1e30f;
#pragma unroll
            for (int nt = 0; nt < 4; nt++)
                tm = fmaxf(tm, fmaxf(s[nt][rg*2], s[nt][rg*2+1]));
            float rs = 0.0f;
#pragma unroll
            for (int nt = 0; nt < 4; nt++) {
                float p0 = exp2f(s[nt][rg*2]   - tm);
                float p1 = exp2f(s[nt][rg*2+1] - tm);
                s[nt][rg*2] = p0; s[nt][rg*2+1] = p1;
                rs += p0 + p1;
            }
            float tw = fmaxf(tm, __shfl_xor_sync(0xffffffffu, tm, 1));
            tw = fmaxf(tw, __shfl_xor_sync(0xffffffffu, tw, 2));
            float mn = fmaxf(mr[rg], tw);
            float resc = (tm < -1e29f) ? 0.0f : exp2f(tm - mn);
            float sc = exp2f(mr[rg] - mn);
            lr[rg] = lr[rg] * sc + rs * resc;
            mr[rg] = mn;
            psc[rg] = sc;
            rsc[rg] = resc;
        }
#pragma unroll
        for (int ot = 0; ot < 8; ot++) {
            O[ot][0] *= psc[0]; O[ot][1] *= psc[0];
            O[ot][2] *= psc[1]; O[ot][3] *= psc[1];
        }
        // ---- P fragments: single fp16 (2-term PV) ----
        uint32_t hiA[2][4];
#pragma unroll
        for (int j2 = 0; j2 < 2; j2++) {
            hiA[j2][0] = hfpair(s[2*j2][0]   * rsc[0], s[2*j2][1]   * rsc[0]);
            hiA[j2][1] = hfpair(s[2*j2][2]   * rsc[1], s[2*j2][3]   * rsc[1]);
            hiA[j2][2] = hfpair(s[2*j2+1][0] * rsc[0], s[2*j2+1][1] * rsc[0]);
            hiA[j2][3] = hfpair(s[2*j2+1][2] * rsc[1], s[2*j2+1][3] * rsc[1]);
        }
        // ---- O += P·V : fp16, 2 terms (Ph·Vh + Ph·Vl) ----
        {
            uint32_t vS = sb + FKV + buf * 32768 + 16384;
            const int rV = lane & 15;
#pragma unroll
            for (int jj = 0; jj < 2; jj++) {
                const int grh = 8 * g + 2 * jj + kgl;
                const int grl = grh + 4;
                uint32_t b4[4][4];
#pragma unroll
                for (int ng = 0; ng < 4; ng++) ldsm4(vS + off256(rV + 16*ng, grh), b4[ng]);
#pragma unroll
                for (int ng = 0; ng < 4; ng++) {
                    uint32_t p0[2] = {b4[ng][0], b4[ng][2]};
                    uint32_t p1[2] = {b4[ng][1], b4[ng][3]};
                    mma16816h(O[ng*2+0], hiA[jj], p0);
                    mma16816h(O[ng*2+1], hiA[jj], p1);
                }
#pragma unroll
                for (int ng = 0; ng < 4; ng++) ldsm4(vS + off256(rV + 16*ng, grl), b4[ng]);
#pragma unroll
                for (int ng = 0; ng < 4; ng++) {
                    uint32_t p0[2] = {b4[ng][0], b4[ng][2]};
                    uint32_t p1[2] = {b4[ng][1], b4[ng][3]};
                    mma16816h(O[ng*2+0], hiA[jj], p0);
                    mma16816h(O[ng*2+1], hiA[jj], p1);
                }
            }
        }
    }
#pragma unroll
    for (int rg = 0; rg < 2; rg++) {
        lr[rg] += __shfl_xor_sync(0xffffffffu, lr[rg], 1);
        lr[rg] += __shfl_xor_sync(0xffffffffu, lr[rg], 2);
    }
    // ---- merge halves ----
    __syncthreads();
    if (g == 1) {
#pragma unroll
        for (int rg = 0; rg < 2; rg++) {
            int r = wm + rowq + rg * 8;
            if ((lane & 3) == 0)
                *reinterpret_cast<float2*>(sm + FML + r * 8) = make_float2(mr[rg], lr[rg]);
#pragma unroll
            for (int nt = 0; nt < 8; nt++) {
                int c = nt * 8 + colq;
                *reinterpret_cast<float2*>(sm + FPS2 + (r * 64 + c) * 4) =
                    make_float2(O[nt][rg*2], O[nt][rg*2+1]);
            }
        }
    }
    __syncthreads();
    if (g == 0) {
        const int h = bh & 15, bb = bh >> 4;
#pragma unroll
        for (int rg = 0; rg < 2; rg++) {
            int rl = wm + rowq + rg * 8;
            float2 ml1 = *reinterpret_cast<float2*>(sm + FML + rl * 8);
            float M = fmaxf(mr[rg], ml1.x);
            float sc0 = exp2f(mr[rg] - M), sc1 = exp2f(ml1.x - M);
            float inv = 1.0f / (lr[rg] * sc0 + ml1.y * sc1);
            int t = qt * 128 + rl;
            uint32_t* dst = reinterpret_cast<uint32_t*>(g_ap + ((size_t)bb * T_ + t) * KD);
#pragma unroll
            for (int nt = 0; nt < 8; nt++) {
                int c = nt * 8 + colq;
                float2 o1 = *reinterpret_cast<float2*>(sm + FPS2 + (rl * 64 + c) * 4);
                float v0 = (O[nt][rg*2] * sc0 + o1.x * sc1) * inv;
                float v1 = (O[nt][rg*2+1] * sc0 + o1.y * sc1) * inv;
                dst[(h * 64 + c) >> 1] = hfpair(v0, v1);
                dst[(1024 + h * 64 + c) >> 1] = hfpair(hflo(v0), hflo(v1));
            }
        }
    }
}

// ---------------- launch ----------------
extern "C" void kernel_launch(void* const* d_in, const int* in_sizes, int n_in,
                              void* d_out, int out_size)
{
    const float* x  = (const float*)d_in[0];
    const float* Wk = (const float*)d_in[1];
    const float* bk = (const float*)d_in[2];
    const float* Wq = (const float*)d_in[3];
    const float* bq = (const float*)d_in[4];
    const float* Wv = (const float*)d_in[5];
    const float* bv = (const float*)d_in[6];
    const float* Wp = (const float*)d_in[7];
    const float* bp = (const float*)d_in[8];
    float* out = (float*)d_out;

    pack_a_kernel<<<(BT_ * D_) / (4 * 256), 256>>>(x);
    pack_w_kernel<<<dim3(32, 32, 4), 256>>>(Wq, Wk, Wv, Wp);

    cudaFuncSetAttribute(qkv_gemm, cudaFuncAttributeMaxDynamicSharedMemorySize, DSMEM);
    cudaFuncSetAttribute(proj_gemm, cudaFuncAttributeMaxDynamicSharedMemorySize, PSMEM);
    cudaFuncSetAttribute(flash_mma, cudaFuncAttributeMaxDynamicSharedMemorySize, FLASH_SMEM);

    qkv_gemm<<<dim3(8, 64, 3), 256, DSMEM>>>(bq, bk, bv);
    flash_mma<<<dim3(T_ / 128, B_ * NH_), FTHREADS, FLASH_SMEM>>>();
    proj_gemm<<<dim3(8, 64), 256, PSMEM>>>(bp, out);
}